// round 9
// baseline (speedup 1.0000x reference)
#include <cuda_runtime.h>
#include <cuda_bf16.h>
#include <math.h>
#include <stdint.h>

#define T      4096
#define DH     64
#define NH     4
#define NB     64
#define DM     512
#define BHN    32
#define SELF_VAL (-5e4f)

__device__ float g_qk [(size_t)BHN * T * DH];
__device__ float g_v  [(size_t)BHN * T * DH];
__device__ int   g_st [BHN * NH * T];
__device__ float g_o  [(size_t)BHN * NH * T * DH];
__device__ float g_lse[BHN * NH * T];
__device__ float g_ctx[(size_t)4 * T * DM];

extern __shared__ float smem[];

// ---------------- packed fp32x2 helpers ----------------
__device__ __forceinline__ unsigned long long bcast2(float x) {
    unsigned long long r; asm("mov.b64 %0, {%1, %1};" : "=l"(r) : "f"(x)); return r;
}
__device__ __forceinline__ float2 unpk2(unsigned long long v) {
    float2 f; asm("mov.b64 {%0, %1}, %2;" : "=f"(f.x), "=f"(f.y) : "l"(v)); return f;
}
#define FMA2(d, a, b) asm("fma.rn.f32x2 %0, %1, %2, %0;" : "+l"(d) : "l"(a), "l"(b))

// ---------------- fp32 GEMM (W_qk: exact, feeds hash argmax) ----------------
__global__ __launch_bounds__(256)
void gemm_qk_kernel(const float* __restrict__ A,
                    const float* __restrict__ Bm)
{
    const int N = 512, K = 512;
    __shared__ float As[2][16][132];
    __shared__ float Bs[2][16][68];

    int tid = threadIdx.x;
    int tx = tid & 15, ty = tid >> 4;
    int bm = blockIdx.y * 128, bn = blockIdx.x * 64;

    int f0 = tid * 2, f1 = tid * 2 + 1;
    int a_row0 = f0 >> 2, a_k0 = (f0 & 3) << 2;
    int a_row1 = f1 >> 2, a_k1 = (f1 & 3) << 2;
    int b_k = tid >> 4, b_n = (tid & 15) << 2;

    float4 ar0, ar1, br;
    unsigned long long acc2[8][2];
    #pragma unroll
    for (int i = 0; i < 8; i++) { acc2[i][0] = 0ull; acc2[i][1] = 0ull; }

#define LDG_TILE(k0)                                                              \
    {   ar0 = *(const float4*)&A[(size_t)(bm + a_row0) * K + (k0) + a_k0];        \
        ar1 = *(const float4*)&A[(size_t)(bm + a_row1) * K + (k0) + a_k1];        \
        br  = *(const float4*)&Bm[(size_t)((k0) + b_k) * N + bn + b_n]; }
#define STS_TILE(buf)                                                             \
    {   As[buf][a_k0 + 0][a_row0] = ar0.x; As[buf][a_k0 + 1][a_row0] = ar0.y;     \
        As[buf][a_k0 + 2][a_row0] = ar0.z; As[buf][a_k0 + 3][a_row0] = ar0.w;     \
        As[buf][a_k1 + 0][a_row1] = ar1.x; As[buf][a_k1 + 1][a_row1] = ar1.y;     \
        As[buf][a_k1 + 2][a_row1] = ar1.z; As[buf][a_k1 + 3][a_row1] = ar1.w;     \
        *(float4*)&Bs[buf][b_k][b_n] = br; }

    LDG_TILE(0); STS_TILE(0); __syncthreads();

    const int NST = K / 16;
    for (int s = 0; s < NST; s++) {
        if (s + 1 < NST) LDG_TILE((s + 1) * 16);
        int buf = s & 1;
        #pragma unroll
        for (int k = 0; k < 16; k++) {
            float4 a0 = *(const float4*)&As[buf][k][ty * 8];
            float4 a1 = *(const float4*)&As[buf][k][ty * 8 + 4];
            ulonglong2 b2 = *(const ulonglong2*)&Bs[buf][k][tx * 4];
            float av[8] = {a0.x, a0.y, a0.z, a0.w, a1.x, a1.y, a1.z, a1.w};
            #pragma unroll
            for (int i = 0; i < 8; i++) {
                unsigned long long ap = bcast2(av[i]);
                FMA2(acc2[i][0], ap, b2.x);
                FMA2(acc2[i][1], ap, b2.y);
            }
        }
        if (s + 1 < NST) STS_TILE((s + 1) & 1);
        __syncthreads();
    }

    #pragma unroll
    for (int i = 0; i < 8; i++) {
        int m = bm + ty * 8 + i;
        float2 p0 = unpk2(acc2[i][0]), p1 = unpk2(acc2[i][1]);
        float vv[4] = {p0.x, p0.y, p1.x, p1.y};
        #pragma unroll
        for (int j = 0; j < 4; j++) {
            int n = bn + tx * 4 + j;
            int b = m >> 12, t = m & 4095;
            int h = n >> 6,  d = n & 63;
            g_qk[(((size_t)(b * 8 + h)) * T + t) * DH + d] = vv[j];
        }
    }
#undef LDG_TILE
#undef STS_TILE
}

// ======== bf16 2-split mma.sync GEMM (W_v merged / W_out + bias) ========
// C[16384,512] = A[16384,512] @ W[512,512], 128x128 block tile, 8 warps.
// A tile: [128 rows][36 words]  (word = bf16x2 over k-pair) -- conflict-free
// B tile: [32 k2][136 words]    (word = bf16x2 over k-pair) -- conflict-free
#define PA 36
#define PB 136
#define AW (128 * PA)     // 4608 words
#define BW (32 * PB)      // 4352 words
#define SMEM_BF (2 * (AW + BW) * 4)   // 71680 B

#define MMA_BF16(c, a, b)                                                         \
    asm volatile("mma.sync.aligned.m16n8k16.row.col.f32.bf16.bf16.f32 "           \
                 "{%0,%1,%2,%3},{%4,%5,%6,%7},{%8,%9},{%0,%1,%2,%3};"             \
                 : "+f"(c[0]), "+f"(c[1]), "+f"(c[2]), "+f"(c[3])                 \
                 : "r"(a[0]), "r"(a[1]), "r"(a[2]), "r"(a[3]), "r"(b[0]), "r"(b[1]))

template <int MODE>   // 1: -> g_v merged ; 2: A=g_ctx, C = acc + bias
__global__ __launch_bounds__(256)
void gemm_bf16_kernel(const float* __restrict__ A, const float* __restrict__ W,
                      const float* __restrict__ bias, float* __restrict__ Cout)
{
    uint32_t* sA0 = (uint32_t*)smem;
    uint32_t* sA1 = sA0 + AW;
    uint32_t* sB0 = sA1 + AW;
    uint32_t* sB1 = sB0 + BW;

    int tid = threadIdx.x, lane = tid & 31, wid = tid >> 5;
    int g = lane >> 2, tq = lane & 3;
    int wm = wid >> 1, wn = wid & 1;
    int m0 = wm * 32, n0 = wn * 64;
    int bm = blockIdx.y * 128, bn = blockIdx.x * 128;
    const float* Ap = (MODE == 2) ? g_ctx : A;

    float acc[2][8][4] = {};

    for (int c = 0; c < 8; c++) {
        int k0 = c * 64;
        if (c > 0) __syncthreads();   // protect smem reuse

        // ---- A: rows wid*16 + rr, k-pair = lane  (banks 4*row+p: conflict-free)
        {
            int p = lane;
            #pragma unroll 4
            for (int rr = 0; rr < 16; rr++) {
                int row = wid * 16 + rr;
                float2 av = *(const float2*)&Ap[(size_t)(bm + row) * 512 + k0 + 2 * p];
                __nv_bfloat162 h0 = __float22bfloat162_rn(av);
                *(__nv_bfloat162*)(sA0 + row * PA + p) = h0;
                float2 f0 = __bfloat1622float2(h0);
                av.x -= f0.x; av.y -= f0.y;
                *(__nv_bfloat162*)(sA1 + row * PA + p) = __float22bfloat162_rn(av);
            }
        }
        // ---- B: k2 = wid*4 + j, n = lane + 32u  (banks 8*k2+q: conflict-free)
        {
            int q = lane;
            #pragma unroll
            for (int j = 0; j < 4; j++) {
                int k2 = wid * 4 + j;
                const float* w0p = &W[(size_t)(k0 + 2 * k2) * 512 + bn];
                const float* w1p = &W[(size_t)(k0 + 2 * k2 + 1) * 512 + bn];
                #pragma unroll
                for (int u = 0; u < 4; u++) {
                    int n = q + 32 * u;
                    float2 wv = make_float2(w0p[n], w1p[n]);
                    __nv_bfloat162 h0 = __float22bfloat162_rn(wv);
                    *(__nv_bfloat162*)(sB0 + k2 * PB + n) = h0;
                    float2 f0 = __bfloat1622float2(h0);
                    wv.x -= f0.x; wv.y -= f0.y;
                    *(__nv_bfloat162*)(sB1 + k2 * PB + n) = __float22bfloat162_rn(wv);
                }
            }
        }
        __syncthreads();

        // ---- compute: 4 k16-steps
        #pragma unroll
        for (int ks = 0; ks < 4; ks++) {
            int kk = tq + 8 * ks;
            uint32_t ah[2][4], al[2][4];
            #pragma unroll
            for (int mi = 0; mi < 2; mi++) {
                int r0 = (m0 + mi * 16 + g) * PA;
                int r1 = (m0 + mi * 16 + g + 8) * PA;
                ah[mi][0] = sA0[r0 + kk];     ah[mi][1] = sA0[r1 + kk];
                ah[mi][2] = sA0[r0 + kk + 4]; ah[mi][3] = sA0[r1 + kk + 4];
                al[mi][0] = sA1[r0 + kk];     al[mi][1] = sA1[r1 + kk];
                al[mi][2] = sA1[r0 + kk + 4]; al[mi][3] = sA1[r1 + kk + 4];
            }
            #pragma unroll
            for (int ni = 0; ni < 8; ni++) {
                int n = n0 + ni * 8 + g;
                uint32_t bh[2], bl[2];
                bh[0] = sB0[kk * PB + n]; bh[1] = sB0[(kk + 4) * PB + n];
                bl[0] = sB1[kk * PB + n]; bl[1] = sB1[(kk + 4) * PB + n];
                #pragma unroll
                for (int mi = 0; mi < 2; mi++) {
                    MMA_BF16(acc[mi][ni], ah[mi], bh);
                    MMA_BF16(acc[mi][ni], ah[mi], bl);
                    MMA_BF16(acc[mi][ni], al[mi], bh);
                }
            }
        }
    }

    // ---- epilogue
    #pragma unroll
    for (int mi = 0; mi < 2; mi++) {
        int m_top = bm + m0 + mi * 16 + g;
        #pragma unroll
        for (int ni = 0; ni < 8; ni++) {
            int n = bn + n0 + ni * 8 + 2 * tq;
            float c0 = acc[mi][ni][0], c1 = acc[mi][ni][1];
            float c2 = acc[mi][ni][2], c3 = acc[mi][ni][3];
            if (MODE == 2) {
                float2 bi2 = *(const float2*)&bias[n];
                *(float2*)&Cout[(size_t)m_top * 512 + n]       = make_float2(c0 + bi2.x, c1 + bi2.y);
                *(float2*)&Cout[(size_t)(m_top + 8) * 512 + n] = make_float2(c2 + bi2.x, c3 + bi2.y);
            } else {
                int h = n >> 6, d = n & 63;
                {
                    int b = m_top >> 12, tp = m_top & 4095;
                    *(float2*)&g_v[(((size_t)(b * 8 + h)) * T + tp) * DH + d] = make_float2(c0, c1);
                }
                {
                    int m2 = m_top + 8;
                    int b = m2 >> 12, tp = m2 & 4095;
                    *(float2*)&g_v[(((size_t)(b * 8 + h)) * T + tp) * DH + d] = make_float2(c2, c3);
                }
            }
        }
    }
}

// ======== hash + stable counting sort ========
__global__ void hash_sort_kernel(const float* __restrict__ rotations)
{
    int bh = blockIdx.x >> 2, r = blockIdx.x & 3;
    __shared__ float rot[64][32];
    __shared__ unsigned char bucket[T];
    __shared__ int hist4[4][NB], offs[NB], tot[NB];
    int tid = threadIdx.x;
    for (int x = tid; x < 64 * 32; x += 256) {
        int d = x >> 5, i = x & 31;
        rot[d][i] = rotations[(d * NH + r) * 32 + i];
    }
    ((int*)hist4)[tid] = 0;
    __syncthreads();
    const float* qkbh = g_qk + (size_t)bh * T * DH;
    for (int t = tid; t < T; t += 256) {
        const float* q = qkbh + (size_t)t * DH;
        float s[32];
        #pragma unroll
        for (int i = 0; i < 32; i++) s[i] = 0.f;
        for (int d4 = 0; d4 < 16; d4++) {
            float4 qv = *(const float4*)&q[d4 * 4];
            #pragma unroll
            for (int i = 0; i < 32; i++) {
                s[i] = fmaf(qv.x, rot[d4 * 4 + 0][i], s[i]);
                s[i] = fmaf(qv.y, rot[d4 * 4 + 1][i], s[i]);
                s[i] = fmaf(qv.z, rot[d4 * 4 + 2][i], s[i]);
                s[i] = fmaf(qv.w, rot[d4 * 4 + 3][i], s[i]);
            }
        }
        float best = -3.4e38f; int bi = 0;
        #pragma unroll
        for (int i = 0; i < 32; i++) { if (s[i] > best) { best = s[i]; bi = i; } }
        #pragma unroll
        for (int i = 0; i < 32; i++) { float v = -s[i]; if (v > best) { best = v; bi = 32 + i; } }
        bucket[t] = (unsigned char)bi;
        atomicAdd(&hist4[t >> 10][bi], 1);
    }
    __syncthreads();
    if (tid < NB)
        tot[tid] = hist4[0][tid] + hist4[1][tid] + hist4[2][tid] + hist4[3][tid];
    __syncthreads();
    if (tid == 0) {
        int run = 0;
        for (int b = 0; b < NB; b++) { offs[b] = run; run += tot[b]; }
    }
    __syncthreads();
    {
        int b = tid & 63, q = tid >> 6;
        int o = offs[b];
        #pragma unroll
        for (int qq = 0; qq < 3; qq++) if (qq < q) o += hist4[qq][b];
        int* stout = g_st + (bh * NH + r) * T;
        int t0 = q << 10;
        for (int t = t0; t < t0 + 1024; t++)
            if (bucket[t] == (unsigned char)b) stout[o++] = t;
    }
}

// ======== attention (fp32 roofline) ========
#define KTP 136
#define VP  68
#define DP  132
#define SMEM_ATTN ((64*KTP + 128*VP + 128 + 64 + 128) * 4)

__global__ __launch_bounds__(256, 3)
void lsh_attn_kernel()
{
    int bh = blockIdx.x >> 8, c = blockIdx.x & 255;
    int r = c >> 6, pc = (c + 255) & 255;
    float* Kt = smem;
    float* Vs = Kt + 64 * KTP;
    float* inv_norm = Vs + 128 * VP;
    float* invs = inv_norm + 128;
    int* kpos = (int*)(invs + 64);
    float* dots = Kt;
    int tid = threadIdx.x;
    if (tid < 128) {
        int g = (tid < 64) ? (c * 64 + tid) : (pc * 64 + tid - 64);
        kpos[tid] = g_st[bh * (NH * T) + g];
    }
    __syncthreads();
    {
        int row = tid >> 1, half = (tid & 1) << 5;
        int p = kpos[row];
        const float* ksrc = g_qk + ((size_t)bh * T + p) * DH + half;
        const float* vsrc = g_v  + ((size_t)bh * T + p) * DH + half;
        float ss = 0.f;
        #pragma unroll
        for (int u = 0; u < 8; u++) {
            float4 kv = *(const float4*)&ksrc[u * 4];
            float4 vv = *(const float4*)&vsrc[u * 4];
            int k = half + u * 4;
            Kt[(k + 0) * KTP + row] = kv.x; Kt[(k + 1) * KTP + row] = kv.y;
            Kt[(k + 2) * KTP + row] = kv.z; Kt[(k + 3) * KTP + row] = kv.w;
            *(float4*)&Vs[row * VP + k] = vv;
            ss = fmaf(kv.x, kv.x, ss); ss = fmaf(kv.y, kv.y, ss);
            ss = fmaf(kv.z, kv.z, ss); ss = fmaf(kv.w, kv.w, ss);
        }
        ss += __shfl_xor_sync(0xffffffffu, ss, 1);
        if ((tid & 1) == 0) inv_norm[row] = 1.0f / fmaxf(sqrtf(ss), 1e-12f);
    }
    __syncthreads();
    int tx = tid & 15, ty = tid >> 4, i0 = ty * 4;
    unsigned long long acc2[4][4];
    #pragma unroll
    for (int i = 0; i < 4; i++)
        #pragma unroll
        for (int p = 0; p < 4; p++) acc2[i][p] = 0ull;
    #pragma unroll 4
    for (int k = 0; k < 64; k++) {
        const float* krow = Kt + k * KTP;
        float4 a = *(const float4*)&krow[i0];
        ulonglong2 bA = *(const ulonglong2*)&krow[4 * tx];
        ulonglong2 bB = *(const ulonglong2*)&krow[64 + 4 * tx];
        float av[4] = {a.x, a.y, a.z, a.w};
        #pragma unroll
        for (int i = 0; i < 4; i++) {
            unsigned long long ap = bcast2(av[i]);
            FMA2(acc2[i][0], ap, bA.x); FMA2(acc2[i][1], ap, bA.y);
            FMA2(acc2[i][2], ap, bB.x); FMA2(acc2[i][3], ap, bB.y);
        }
    }
    float4 in0 = *(const float4*)&inv_norm[4 * tx];
    float4 in1 = *(const float4*)&inv_norm[64 + 4 * tx];
    int4 kp0 = *(const int4*)&kpos[4 * tx];
    int4 kp1 = *(const int4*)&kpos[64 + 4 * tx];
    float inj[8] = {in0.x, in0.y, in0.z, in0.w, in1.x, in1.y, in1.z, in1.w};
    int   pj[8]  = {kp0.x, kp0.y, kp0.z, kp0.w, kp1.x, kp1.y, kp1.z, kp1.w};
    float m8[4][8];
    #pragma unroll
    for (int i = 0; i < 4; i++) {
        int qp = kpos[i0 + i];
        float2 p0 = unpk2(acc2[i][0]), p1 = unpk2(acc2[i][1]);
        float2 p2 = unpk2(acc2[i][2]), p3 = unpk2(acc2[i][3]);
        float vj[8] = {p0.x, p0.y, p1.x, p1.y, p2.x, p2.y, p3.x, p3.y};
        #pragma unroll
        for (int j = 0; j < 8; j++) {
            float v = vj[j] * inj[j] * 0.125f;
            m8[i][j] = (pj[j] == qp) ? SELF_VAL : v;
        }
    }
    __syncthreads();
    #pragma unroll
    for (int i = 0; i < 4; i++) {
        float* drow = dots + (i0 + i) * DP;
        *(float4*)&drow[4 * tx]      = make_float4(m8[i][0], m8[i][1], m8[i][2], m8[i][3]);
        *(float4*)&drow[64 + 4 * tx] = make_float4(m8[i][4], m8[i][5], m8[i][6], m8[i][7]);
    }
    __syncthreads();
    {
        int row = tid >> 2, seg = tid & 3;
        float* drow = dots + row * DP;
        float mp = -3.4e38f;
        #pragma unroll
        for (int k = 0; k < 32; k++) mp = fmaxf(mp, drow[seg + 4 * k]);
        mp = fmaxf(mp, __shfl_xor_sync(0xffffffffu, mp, 1));
        mp = fmaxf(mp, __shfl_xor_sync(0xffffffffu, mp, 2));
        float sp = 0.f;
        #pragma unroll
        for (int k = 0; k < 32; k++) {
            float e = __expf(drow[seg + 4 * k] - mp);
            drow[seg + 4 * k] = e; sp += e;
        }
        sp += __shfl_xor_sync(0xffffffffu, sp, 1);
        sp += __shfl_xor_sync(0xffffffffu, sp, 2);
        if (seg == 0) {
            invs[row] = 1.0f / sp;
            g_lse[((size_t)bh * NH + r) * T + kpos[row]] = mp + logf(sp);
        }
    }
    __syncthreads();
    {
        unsigned long long pv2[4][2];
        #pragma unroll
        for (int i = 0; i < 4; i++) { pv2[i][0] = 0ull; pv2[i][1] = 0ull; }
        #pragma unroll 2
        for (int k = 0; k < 128; k += 2) {
            float2 pr[4];
            #pragma unroll
            for (int i = 0; i < 4; i++) pr[i] = *(const float2*)&dots[(i0 + i) * DP + k];
            ulonglong2 v0 = *(const ulonglong2*)&Vs[k * VP + 4 * tx];
            ulonglong2 v1 = *(const ulonglong2*)&Vs[(k + 1) * VP + 4 * tx];
            #pragma unroll
            for (int i = 0; i < 4; i++) {
                unsigned long long pa = bcast2(pr[i].x);
                FMA2(pv2[i][0], pa, v0.x); FMA2(pv2[i][1], pa, v0.y);
                unsigned long long pb = bcast2(pr[i].y);
                FMA2(pv2[i][0], pb, v1.x); FMA2(pv2[i][1], pb, v1.y);
            }
        }
        #pragma unroll
        for (int i = 0; i < 4; i++) {
            float sc = invs[i0 + i];
            float2 a = unpk2(pv2[i][0]), b = unpk2(pv2[i][1]);
            size_t base = (((size_t)bh * NH + r) * T + kpos[i0 + i]) * DH;
            *(float4*)&g_o[base + 4 * tx] = make_float4(a.x * sc, a.y * sc, b.x * sc, b.y * sc);
        }
    }
}

// ======== combine ========
__global__ void combine_kernel()
{
    int idx = blockIdx.x * 256 + threadIdx.x;
    int d = idx & 63, pos = (idx >> 6) & 4095, bh = idx >> 18;
    float l[4];
    #pragma unroll
    for (int r = 0; r < 4; r++) l[r] = g_lse[((size_t)bh * 4 + r) * T + pos];
    float m = fmaxf(fmaxf(l[0], l[1]), fmaxf(l[2], l[3]));
    float w[4], ws = 0.f;
    #pragma unroll
    for (int r = 0; r < 4; r++) { w[r] = __expf(l[r] - m); ws += w[r]; }
    float o = 0.f;
    #pragma unroll
    for (int r = 0; r < 4; r++)
        o += w[r] * g_o[(((size_t)bh * 4 + r) * T + pos) * DH + d];
    o /= ws;
    int b = bh >> 3, h = bh & 7;
    g_ctx[((size_t)b * T + pos) * DM + h * 64 + d] = o;
}

// ======== launch ========
extern "C" void kernel_launch(void* const* d_in, const int* in_sizes, int n_in,
                              void* d_out, int out_size)
{
    (void)in_sizes; (void)n_in; (void)out_size;
    const float* queries   = (const float*)d_in[0];
    const float* W_qk      = (const float*)d_in[3];
    const float* W_v       = (const float*)d_in[4];
    const float* W_out     = (const float*)d_in[5];
    const float* b_out     = (const float*)d_in[6];
    const float* rotations = (const float*)d_in[7];
    float* out = (float*)d_out;

    static cudaStream_t s_aux = nullptr;
    static cudaEvent_t ev_fork = nullptr, ev_join = nullptr;
    if (!s_aux) {
        cudaStreamCreateWithFlags(&s_aux, cudaStreamNonBlocking);
        cudaEventCreateWithFlags(&ev_fork, cudaEventDisableTiming);
        cudaEventCreateWithFlags(&ev_join, cudaEventDisableTiming);
    }

    dim3 gq(512 / 64, 16384 / 128);     // fp32 qk gemm
    dim3 gb(512 / 128, 16384 / 128);    // bf16 mma gemms

    cudaFuncSetAttribute(gemm_bf16_kernel<1>, cudaFuncAttributeMaxDynamicSharedMemorySize, SMEM_BF);
    cudaFuncSetAttribute(gemm_bf16_kernel<2>, cudaFuncAttributeMaxDynamicSharedMemorySize, SMEM_BF);
    cudaFuncSetAttribute(lsh_attn_kernel, cudaFuncAttributeMaxDynamicSharedMemorySize, SMEM_ATTN);

    // fork: W_v GEMM concurrent with W_qk GEMM + hash
    cudaEventRecord(ev_fork, 0);
    cudaStreamWaitEvent(s_aux, ev_fork, 0);
    gemm_bf16_kernel<1><<<gb, 256, SMEM_BF, s_aux>>>(queries, W_v, nullptr, nullptr);
    cudaEventRecord(ev_join, s_aux);

    gemm_qk_kernel<<<gq, 256>>>(queries, W_qk);
    hash_sort_kernel<<<BHN * NH, 256>>>(rotations);

    cudaStreamWaitEvent(0, ev_join, 0);

    lsh_attn_kernel<<<BHN * 256, 256, SMEM_ATTN>>>();

    combine_kernel<<<(BHN * T * DH) / 256, 256>>>();

    gemm_bf16_kernel<2><<<gb, 256, SMEM_BF>>>(nullptr, W_out, b_out, out);
}

// round 10
// speedup vs baseline: 1.6230x; 1.6230x over previous
#include <cuda_runtime.h>
#include <cuda_bf16.h>
#include <math.h>
#include <stdint.h>

#define T      4096
#define DH     64
#define NH     4
#define NB     64
#define DM     512
#define BHN    32
#define SELF_VAL (-5e4f)

__device__ float g_qk [(size_t)BHN * T * DH];
__device__ float g_v  [(size_t)BHN * T * DH];
__device__ int   g_st [BHN * NH * T];
__device__ float g_o  [(size_t)BHN * NH * T * DH];
__device__ float g_lse[BHN * NH * T];
__device__ float g_ctx[(size_t)4 * T * DM];

extern __shared__ float smem[];

// ---------------- packed fp32x2 helpers ----------------
__device__ __forceinline__ unsigned long long bcast2(float x) {
    unsigned long long r; asm("mov.b64 %0, {%1, %1};" : "=l"(r) : "f"(x)); return r;
}
__device__ __forceinline__ float2 unpk2(unsigned long long v) {
    float2 f; asm("mov.b64 {%0, %1}, %2;" : "=f"(f.x), "=f"(f.y) : "l"(v)); return f;
}
#define FMA2(d, a, b) asm("fma.rn.f32x2 %0, %1, %2, %0;" : "+l"(d) : "l"(a), "l"(b))

// ---------------- bf16 pack helpers ----------------
__device__ __forceinline__ uint32_t pkbf(float x, float y) {
    __nv_bfloat162 h = __float22bfloat162_rn(make_float2(x, y));
    return *(uint32_t*)&h;
}
__device__ __forceinline__ float2 upbf(uint32_t u) {
    __nv_bfloat162 h = *(__nv_bfloat162*)&u;
    return __bfloat1622float2(h);
}

#define MMA_BF16(c, a, b)                                                         \
    asm volatile("mma.sync.aligned.m16n8k16.row.col.f32.bf16.bf16.f32 "           \
                 "{%0,%1,%2,%3},{%4,%5,%6,%7},{%8,%9},{%0,%1,%2,%3};"             \
                 : "+f"(c[0]), "+f"(c[1]), "+f"(c[2]), "+f"(c[3])                 \
                 : "r"(a[0]), "r"(a[1]), "r"(a[2]), "r"(a[3]), "r"(b[0]), "r"(b[1]))

// ---------------- fp32 GEMM (W_qk: exact, feeds hash argmax) ----------------
__global__ __launch_bounds__(256)
void gemm_qk_kernel(const float* __restrict__ A,
                    const float* __restrict__ Bm)
{
    const int N = 512, K = 512;
    __shared__ float As[2][16][132];
    __shared__ float Bs[2][16][68];

    int tid = threadIdx.x;
    int tx = tid & 15, ty = tid >> 4;
    int bm = blockIdx.y * 128, bn = blockIdx.x * 64;

    int f0 = tid * 2, f1 = tid * 2 + 1;
    int a_row0 = f0 >> 2, a_k0 = (f0 & 3) << 2;
    int a_row1 = f1 >> 2, a_k1 = (f1 & 3) << 2;
    int b_k = tid >> 4, b_n = (tid & 15) << 2;

    float4 ar0, ar1, br;
    unsigned long long acc2[8][2];
    #pragma unroll
    for (int i = 0; i < 8; i++) { acc2[i][0] = 0ull; acc2[i][1] = 0ull; }

#define LDG_TILE(k0)                                                              \
    {   ar0 = *(const float4*)&A[(size_t)(bm + a_row0) * K + (k0) + a_k0];        \
        ar1 = *(const float4*)&A[(size_t)(bm + a_row1) * K + (k0) + a_k1];        \
        br  = *(const float4*)&Bm[(size_t)((k0) + b_k) * N + bn + b_n]; }
#define STS_TILE(buf)                                                             \
    {   As[buf][a_k0 + 0][a_row0] = ar0.x; As[buf][a_k0 + 1][a_row0] = ar0.y;     \
        As[buf][a_k0 + 2][a_row0] = ar0.z; As[buf][a_k0 + 3][a_row0] = ar0.w;     \
        As[buf][a_k1 + 0][a_row1] = ar1.x; As[buf][a_k1 + 1][a_row1] = ar1.y;     \
        As[buf][a_k1 + 2][a_row1] = ar1.z; As[buf][a_k1 + 3][a_row1] = ar1.w;     \
        *(float4*)&Bs[buf][b_k][b_n] = br; }

    LDG_TILE(0); STS_TILE(0); __syncthreads();

    const int NST = K / 16;
    for (int s = 0; s < NST; s++) {
        if (s + 1 < NST) LDG_TILE((s + 1) * 16);
        int buf = s & 1;
        #pragma unroll
        for (int k = 0; k < 16; k++) {
            float4 a0 = *(const float4*)&As[buf][k][ty * 8];
            float4 a1 = *(const float4*)&As[buf][k][ty * 8 + 4];
            ulonglong2 b2 = *(const ulonglong2*)&Bs[buf][k][tx * 4];
            float av[8] = {a0.x, a0.y, a0.z, a0.w, a1.x, a1.y, a1.z, a1.w};
            #pragma unroll
            for (int i = 0; i < 8; i++) {
                unsigned long long ap = bcast2(av[i]);
                FMA2(acc2[i][0], ap, b2.x);
                FMA2(acc2[i][1], ap, b2.y);
            }
        }
        if (s + 1 < NST) STS_TILE((s + 1) & 1);
        __syncthreads();
    }

    #pragma unroll
    for (int i = 0; i < 8; i++) {
        int m = bm + ty * 8 + i;
        float2 p0 = unpk2(acc2[i][0]), p1 = unpk2(acc2[i][1]);
        float vv[4] = {p0.x, p0.y, p1.x, p1.y};
        #pragma unroll
        for (int j = 0; j < 4; j++) {
            int n = bn + tx * 4 + j;
            int b = m >> 12, t = m & 4095;
            int h = n >> 6,  d = n & 63;
            g_qk[(((size_t)(b * 8 + h)) * T + t) * DH + d] = vv[j];
        }
    }
#undef LDG_TILE
#undef STS_TILE
}

// ======== bf16 2-split mma.sync GEMM (W_v merged / W_out + bias) ========
#define PA 36
#define PB 136
#define AW (128 * PA)
#define BW (32 * PB)
#define SMEM_BF (2 * (AW + BW) * 4)

template <int MODE>   // 1: -> g_v merged ; 2: A=g_ctx, C = acc + bias
__global__ __launch_bounds__(256)
void gemm_bf16_kernel(const float* __restrict__ A, const float* __restrict__ W,
                      const float* __restrict__ bias, float* __restrict__ Cout)
{
    uint32_t* sA0 = (uint32_t*)smem;
    uint32_t* sA1 = sA0 + AW;
    uint32_t* sB0 = sA1 + AW;
    uint32_t* sB1 = sB0 + BW;

    int tid = threadIdx.x, lane = tid & 31, wid = tid >> 5;
    int g = lane >> 2, tq = lane & 3;
    int wm = wid >> 1, wn = wid & 1;
    int m0 = wm * 32, n0 = wn * 64;
    int bm = blockIdx.y * 128, bn = blockIdx.x * 128;
    const float* Ap = (MODE == 2) ? g_ctx : A;

    float acc[2][8][4] = {};

    for (int c = 0; c < 8; c++) {
        int k0 = c * 64;
        if (c > 0) __syncthreads();

        {
            int p = lane;
            #pragma unroll 4
            for (int rr = 0; rr < 16; rr++) {
                int row = wid * 16 + rr;
                float2 av = *(const float2*)&Ap[(size_t)(bm + row) * 512 + k0 + 2 * p];
                uint32_t h0 = pkbf(av.x, av.y);
                sA0[row * PA + p] = h0;
                float2 f0 = upbf(h0);
                sA1[row * PA + p] = pkbf(av.x - f0.x, av.y - f0.y);
            }
        }
        {
            int q = lane;
            #pragma unroll
            for (int j = 0; j < 4; j++) {
                int k2 = wid * 4 + j;
                const float* w0p = &W[(size_t)(k0 + 2 * k2) * 512 + bn];
                const float* w1p = &W[(size_t)(k0 + 2 * k2 + 1) * 512 + bn];
                #pragma unroll
                for (int u = 0; u < 4; u++) {
                    int n = q + 32 * u;
                    uint32_t h0 = pkbf(w0p[n], w1p[n]);
                    sB0[k2 * PB + n] = h0;
                    float2 f0 = upbf(h0);
                    sB1[k2 * PB + n] = pkbf(w0p[n] - f0.x, w1p[n] - f0.y);
                }
            }
        }
        __syncthreads();

        #pragma unroll
        for (int ks = 0; ks < 4; ks++) {
            int kk = tq + 8 * ks;
            uint32_t ah[2][4], al[2][4];
            #pragma unroll
            for (int mi = 0; mi < 2; mi++) {
                int r0 = (m0 + mi * 16 + g) * PA;
                int r1 = (m0 + mi * 16 + g + 8) * PA;
                ah[mi][0] = sA0[r0 + kk];     ah[mi][1] = sA0[r1 + kk];
                ah[mi][2] = sA0[r0 + kk + 4]; ah[mi][3] = sA0[r1 + kk + 4];
                al[mi][0] = sA1[r0 + kk];     al[mi][1] = sA1[r1 + kk];
                al[mi][2] = sA1[r0 + kk + 4]; al[mi][3] = sA1[r1 + kk + 4];
            }
            #pragma unroll
            for (int ni = 0; ni < 8; ni++) {
                int n = n0 + ni * 8 + g;
                uint32_t bhv[2], blv[2];
                bhv[0] = sB0[kk * PB + n]; bhv[1] = sB0[(kk + 4) * PB + n];
                blv[0] = sB1[kk * PB + n]; blv[1] = sB1[(kk + 4) * PB + n];
                #pragma unroll
                for (int mi = 0; mi < 2; mi++) {
                    MMA_BF16(acc[mi][ni], ah[mi], bhv);
                    MMA_BF16(acc[mi][ni], ah[mi], blv);
                    MMA_BF16(acc[mi][ni], al[mi], bhv);
                }
            }
        }
    }

    #pragma unroll
    for (int mi = 0; mi < 2; mi++) {
        int m_top = bm + m0 + mi * 16 + g;
        #pragma unroll
        for (int ni = 0; ni < 8; ni++) {
            int n = bn + n0 + ni * 8 + 2 * tq;
            float c0 = acc[mi][ni][0], c1 = acc[mi][ni][1];
            float c2 = acc[mi][ni][2], c3 = acc[mi][ni][3];
            if (MODE == 2) {
                float2 bi2 = *(const float2*)&bias[n];
                *(float2*)&Cout[(size_t)m_top * 512 + n]       = make_float2(c0 + bi2.x, c1 + bi2.y);
                *(float2*)&Cout[(size_t)(m_top + 8) * 512 + n] = make_float2(c2 + bi2.x, c3 + bi2.y);
            } else {
                int h = n >> 6, d = n & 63;
                {
                    int b = m_top >> 12, tp = m_top & 4095;
                    *(float2*)&g_v[(((size_t)(b * 8 + h)) * T + tp) * DH + d] = make_float2(c0, c1);
                }
                {
                    int m2 = m_top + 8;
                    int b = m2 >> 12, tp = m2 & 4095;
                    *(float2*)&g_v[(((size_t)(b * 8 + h)) * T + tp) * DH + d] = make_float2(c2, c3);
                }
            }
        }
    }
}

// ======== hash + stable counting sort ========
__global__ void hash_sort_kernel(const float* __restrict__ rotations)
{
    int bh = blockIdx.x >> 2, r = blockIdx.x & 3;
    __shared__ float rot[64][32];
    __shared__ unsigned char bucket[T];
    __shared__ int hist4[4][NB], offs[NB], tot[NB];
    int tid = threadIdx.x;
    for (int x = tid; x < 64 * 32; x += 256) {
        int d = x >> 5, i = x & 31;
        rot[d][i] = rotations[(d * NH + r) * 32 + i];
    }
    ((int*)hist4)[tid] = 0;
    __syncthreads();
    const float* qkbh = g_qk + (size_t)bh * T * DH;
    for (int t = tid; t < T; t += 256) {
        const float* q = qkbh + (size_t)t * DH;
        float s[32];
        #pragma unroll
        for (int i = 0; i < 32; i++) s[i] = 0.f;
        for (int d4 = 0; d4 < 16; d4++) {
            float4 qv = *(const float4*)&q[d4 * 4];
            #pragma unroll
            for (int i = 0; i < 32; i++) {
                s[i] = fmaf(qv.x, rot[d4 * 4 + 0][i], s[i]);
                s[i] = fmaf(qv.y, rot[d4 * 4 + 1][i], s[i]);
                s[i] = fmaf(qv.z, rot[d4 * 4 + 2][i], s[i]);
                s[i] = fmaf(qv.w, rot[d4 * 4 + 3][i], s[i]);
            }
        }
        float best = -3.4e38f; int bi = 0;
        #pragma unroll
        for (int i = 0; i < 32; i++) { if (s[i] > best) { best = s[i]; bi = i; } }
        #pragma unroll
        for (int i = 0; i < 32; i++) { float v = -s[i]; if (v > best) { best = v; bi = 32 + i; } }
        bucket[t] = (unsigned char)bi;
        atomicAdd(&hist4[t >> 10][bi], 1);
    }
    __syncthreads();
    if (tid < NB)
        tot[tid] = hist4[0][tid] + hist4[1][tid] + hist4[2][tid] + hist4[3][tid];
    __syncthreads();
    if (tid == 0) {
        int run = 0;
        for (int b = 0; b < NB; b++) { offs[b] = run; run += tot[b]; }
    }
    __syncthreads();
    {
        int b = tid & 63, q = tid >> 6;
        int o = offs[b];
        #pragma unroll
        for (int qq = 0; qq < 3; qq++) if (qq < q) o += hist4[qq][b];
        int* stout = g_st + (bh * NH + r) * T;
        int t0 = q << 10;
        for (int t = t0; t < t0 + 1024; t++)
            if (bucket[t] == (unsigned char)b) stout[o++] = t;
    }
}

// ======== attention via bf16 mma 2-split ========
// Kb: [128 rows][36 words]  (word = bf16x2 over k-pair), hi + lo
// Vt: [64 d][68 words]      (word = bf16x2 over row-pair), hi + lo, overlays Kb
// smem: Kb 2*4608 words + inv_norm 128 + kpos 128
#define SMEM_ATTN2 ((2 * 128 * 36 + 256) * 4)

__global__ __launch_bounds__(128, 3)
void lsh_attn_mma_kernel()
{
    uint32_t* KbH = (uint32_t*)smem;
    uint32_t* KbL = KbH + 128 * 36;
    uint32_t* VtH = KbH;                  // overlay (Kb dead before V gather)
    uint32_t* VtL = VtH + 64 * 68;        // 8704 <= 9216 words
    float* inv_norm = (float*)(KbH + 2 * 128 * 36);
    int*   kpos     = (int*)(inv_norm + 128);

    int tid = threadIdx.x, lane = tid & 31, warp = tid >> 5;
    int g = lane >> 2, tq = lane & 3;
    int bh = blockIdx.x >> 8, c = blockIdx.x & 255;
    int r = c >> 6, pc = (c + 255) & 255;

    {
        int gi = (tid < 64) ? (c * 64 + tid) : (pc * 64 + tid - 64);
        kpos[tid] = g_st[bh * (NH * T) + gi];
    }
    __syncthreads();

    // ---- K gather: warp w rows 32w..32w+31; lane = k-pair word; fp32 norm via shfl
    for (int rr = 0; rr < 32; rr++) {
        int row = warp * 32 + rr;
        float2 f2 = ((const float2*)(g_qk + ((size_t)bh * T + kpos[row]) * DH))[lane];
        float part = f2.x * f2.x + f2.y * f2.y;
        part += __shfl_xor_sync(0xffffffffu, part, 16);
        part += __shfl_xor_sync(0xffffffffu, part, 8);
        part += __shfl_xor_sync(0xffffffffu, part, 4);
        part += __shfl_xor_sync(0xffffffffu, part, 2);
        part += __shfl_xor_sync(0xffffffffu, part, 1);
        if (lane == 0) inv_norm[row] = 1.0f / fmaxf(sqrtf(part), 1e-12f);
        uint32_t hw = pkbf(f2.x, f2.y);
        KbH[row * 36 + lane] = hw;
        float2 hf = upbf(hw);
        KbL[row * 36 + lane] = pkbf(f2.x - hf.x, f2.y - hf.y);
    }
    __syncthreads();

    // ---- QK^T: warp w -> rows m0..m0+15, all 128 cols (16 n8-tiles)
    int m0 = warp * 16;
    float acc[16][4];
    #pragma unroll
    for (int j = 0; j < 16; j++)
        #pragma unroll
        for (int x = 0; x < 4; x++) acc[j][x] = 0.f;

    int ra = (m0 + g) * 36, rb = (m0 + g + 8) * 36;
    #pragma unroll
    for (int kt = 0; kt < 4; kt++) {
        int kw = kt * 8 + tq;
        uint32_t ah[4] = {KbH[ra + kw], KbH[rb + kw], KbH[ra + kw + 4], KbH[rb + kw + 4]};
        uint32_t al[4] = {KbL[ra + kw], KbL[rb + kw], KbL[ra + kw + 4], KbL[rb + kw + 4]};
        #pragma unroll
        for (int j = 0; j < 16; j++) {
            int bn = (8 * j + g) * 36;
            uint32_t bhv[2] = {KbH[bn + kw], KbH[bn + kw + 4]};
            uint32_t blv[2] = {KbL[bn + kw], KbL[bn + kw + 4]};
            MMA_BF16(acc[j], ah, bhv);
            MMA_BF16(acc[j], ah, blv);
            MMA_BF16(acc[j], al, bhv);
        }
    }

    // ---- scale + self-mask (C frag: rows g,g+8; cols 8j+2tq,+1)
    int r0 = m0 + g, r1 = r0 + 8;
    int qp0 = kpos[r0], qp1 = kpos[r1];
    #pragma unroll
    for (int j = 0; j < 16; j++) {
        int n = 8 * j + 2 * tq;
        float in0 = inv_norm[n], in1 = inv_norm[n + 1];
        int kc0 = kpos[n], kc1 = kpos[n + 1];
        acc[j][0] = (kc0 == qp0) ? SELF_VAL : acc[j][0] * in0 * 0.125f;
        acc[j][1] = (kc1 == qp0) ? SELF_VAL : acc[j][1] * in1 * 0.125f;
        acc[j][2] = (kc0 == qp1) ? SELF_VAL : acc[j][2] * in0 * 0.125f;
        acc[j][3] = (kc1 == qp1) ? SELF_VAL : acc[j][3] * in1 * 0.125f;
    }

    // ---- softmax on fragments (quad shfl: lanes of a row differ only in tq)
    float mA = -3.4e38f, mB = -3.4e38f;
    #pragma unroll
    for (int j = 0; j < 16; j++) {
        mA = fmaxf(mA, fmaxf(acc[j][0], acc[j][1]));
        mB = fmaxf(mB, fmaxf(acc[j][2], acc[j][3]));
    }
    mA = fmaxf(mA, __shfl_xor_sync(0xffffffffu, mA, 1));
    mA = fmaxf(mA, __shfl_xor_sync(0xffffffffu, mA, 2));
    mB = fmaxf(mB, __shfl_xor_sync(0xffffffffu, mB, 1));
    mB = fmaxf(mB, __shfl_xor_sync(0xffffffffu, mB, 2));
    float sA = 0.f, sB = 0.f;
    #pragma unroll
    for (int j = 0; j < 16; j++) {
        acc[j][0] = __expf(acc[j][0] - mA); sA += acc[j][0];
        acc[j][1] = __expf(acc[j][1] - mA); sA += acc[j][1];
        acc[j][2] = __expf(acc[j][2] - mB); sB += acc[j][2];
        acc[j][3] = __expf(acc[j][3] - mB); sB += acc[j][3];
    }
    sA += __shfl_xor_sync(0xffffffffu, sA, 1);
    sA += __shfl_xor_sync(0xffffffffu, sA, 2);
    sB += __shfl_xor_sync(0xffffffffu, sB, 1);
    sB += __shfl_xor_sync(0xffffffffu, sB, 2);
    if (tq == 0) {
        size_t lb = ((size_t)bh * NH + r) * T;
        g_lse[lb + qp0] = mA + logf(sA);
        g_lse[lb + qp1] = mB + logf(sB);
    }
    float invA = 1.0f / sA, invB = 1.0f / sB;

    // ---- P -> A-fragments (pure register repack; C n-tile pair == A k16-tile)
    uint32_t Ph[8][4], Pl[8][4];
    #pragma unroll
    for (int kt2 = 0; kt2 < 8; kt2++) {
        int j0 = 2 * kt2, j1 = 2 * kt2 + 1;
        Ph[kt2][0] = pkbf(acc[j0][0], acc[j0][1]);
        Ph[kt2][1] = pkbf(acc[j0][2], acc[j0][3]);
        Ph[kt2][2] = pkbf(acc[j1][0], acc[j1][1]);
        Ph[kt2][3] = pkbf(acc[j1][2], acc[j1][3]);
        float2 f;
        f = upbf(Ph[kt2][0]); Pl[kt2][0] = pkbf(acc[j0][0] - f.x, acc[j0][1] - f.y);
        f = upbf(Ph[kt2][1]); Pl[kt2][1] = pkbf(acc[j0][2] - f.x, acc[j0][3] - f.y);
        f = upbf(Ph[kt2][2]); Pl[kt2][2] = pkbf(acc[j1][0] - f.x, acc[j1][1] - f.y);
        f = upbf(Ph[kt2][3]); Pl[kt2][3] = pkbf(acc[j1][2] - f.x, acc[j1][3] - f.y);
    }
    __syncthreads();   // all Kb reads done -> overlay with Vt

    // ---- V gather transposed: warp w covers row-pairs 16w..16w+15
    for (int i = 0; i < 16; i++) {
        int k2v = warp * 16 + i;
        const float* va = g_v + ((size_t)bh * T + kpos[2 * k2v]) * DH;
        const float* vb = g_v + ((size_t)bh * T + kpos[2 * k2v + 1]) * DH;
        #pragma unroll
        for (int h2 = 0; h2 < 2; h2++) {
            int d = lane + 32 * h2;
            float2 f2 = make_float2(va[d], vb[d]);
            uint32_t hw = pkbf(f2.x, f2.y);
            VtH[d * 68 + k2v] = hw;
            float2 hf = upbf(hw);
            VtL[d * 68 + k2v] = pkbf(f2.x - hf.x, f2.y - hf.y);
        }
    }
    __syncthreads();

    // ---- PV: rows m0..m0+15, dh=64 (8 n8-tiles), k=128 (8 k16-tiles)
    float oacc[8][4];
    #pragma unroll
    for (int j = 0; j < 8; j++)
        #pragma unroll
        for (int x = 0; x < 4; x++) oacc[j][x] = 0.f;

    #pragma unroll
    for (int kt2 = 0; kt2 < 8; kt2++) {
        int kw = kt2 * 8 + tq;
        #pragma unroll
        for (int j2 = 0; j2 < 8; j2++) {
            int vn = (8 * j2 + g) * 68;
            uint32_t bhv[2] = {VtH[vn + kw], VtH[vn + kw + 4]};
            uint32_t blv[2] = {VtL[vn + kw], VtL[vn + kw + 4]};
            MMA_BF16(oacc[j2], Ph[kt2], bhv);
            MMA_BF16(oacc[j2], Ph[kt2], blv);
            MMA_BF16(oacc[j2], Pl[kt2], bhv);
        }
    }

    // ---- epilogue: 1/sum folded, scatter to g_o at original positions
    {
        size_t lb = ((size_t)bh * NH + r) * T;
        size_t b0 = (lb + qp0) * DH;
        size_t b1 = (lb + qp1) * DH;
        #pragma unroll
        for (int j2 = 0; j2 < 8; j2++) {
            int d0 = 8 * j2 + 2 * tq;
            *(float2*)&g_o[b0 + d0] = make_float2(oacc[j2][0] * invA, oacc[j2][1] * invA);
            *(float2*)&g_o[b1 + d0] = make_float2(oacc[j2][2] * invB, oacc[j2][3] * invB);
        }
    }
}

// ======== combine ========
__global__ void combine_kernel()
{
    int idx = blockIdx.x * 256 + threadIdx.x;
    int d = idx & 63, pos = (idx >> 6) & 4095, bh = idx >> 18;
    float l[4];
    #pragma unroll
    for (int r = 0; r < 4; r++) l[r] = g_lse[((size_t)bh * 4 + r) * T + pos];
    float m = fmaxf(fmaxf(l[0], l[1]), fmaxf(l[2], l[3]));
    float w[4], ws = 0.f;
    #pragma unroll
    for (int r = 0; r < 4; r++) { w[r] = __expf(l[r] - m); ws += w[r]; }
    float o = 0.f;
    #pragma unroll
    for (int r = 0; r < 4; r++)
        o += w[r] * g_o[(((size_t)bh * 4 + r) * T + pos) * DH + d];
    o /= ws;
    int b = bh >> 3, h = bh & 7;
    g_ctx[((size_t)b * T + pos) * DM + h * 64 + d] = o;
}

// ======== launch ========
extern "C" void kernel_launch(void* const* d_in, const int* in_sizes, int n_in,
                              void* d_out, int out_size)
{
    (void)in_sizes; (void)n_in; (void)out_size;
    const float* queries   = (const float*)d_in[0];
    const float* W_qk      = (const float*)d_in[3];
    const float* W_v       = (const float*)d_in[4];
    const float* W_out     = (const float*)d_in[5];
    const float* b_out     = (const float*)d_in[6];
    const float* rotations = (const float*)d_in[7];
    float* out = (float*)d_out;

    static cudaStream_t s_aux = nullptr;
    static cudaEvent_t ev_fork = nullptr, ev_join = nullptr;
    if (!s_aux) {
        cudaStreamCreateWithFlags(&s_aux, cudaStreamNonBlocking);
        cudaEventCreateWithFlags(&ev_fork, cudaEventDisableTiming);
        cudaEventCreateWithFlags(&ev_join, cudaEventDisableTiming);
    }

    dim3 gq(512 / 64, 16384 / 128);
    dim3 gb(512 / 128, 16384 / 128);

    cudaFuncSetAttribute(gemm_bf16_kernel<1>, cudaFuncAttributeMaxDynamicSharedMemorySize, SMEM_BF);
    cudaFuncSetAttribute(gemm_bf16_kernel<2>, cudaFuncAttributeMaxDynamicSharedMemorySize, SMEM_BF);
    cudaFuncSetAttribute(lsh_attn_mma_kernel, cudaFuncAttributeMaxDynamicSharedMemorySize, SMEM_ATTN2);

    cudaEventRecord(ev_fork, 0);
    cudaStreamWaitEvent(s_aux, ev_fork, 0);
    gemm_bf16_kernel<1><<<gb, 256, SMEM_BF, s_aux>>>(queries, W_v, nullptr, nullptr);
    cudaEventRecord(ev_join, s_aux);

    gemm_qk_kernel<<<gq, 256>>>(queries, W_qk);
    hash_sort_kernel<<<BHN * NH, 256>>>(rotations);

    cudaStreamWaitEvent(0, ev_join, 0);

    lsh_attn_mma_kernel<<<BHN * 256, 128, SMEM_ATTN2>>>();

    combine_kernel<<<(BHN * T * DH) / 256, 256>>>();

    gemm_bf16_kernel<2><<<gb, 256, SMEM_BF>>>(nullptr, W_out, b_out, out);
}

// round 11
// speedup vs baseline: 1.7854x; 1.1001x over previous
#include <cuda_runtime.h>
#include <cuda_bf16.h>
#include <math.h>
#include <stdint.h>

#define T      4096
#define DH     64
#define NH     4
#define NB     64
#define DM     512
#define BHN    32
#define SELF_VAL (-5e4f)

__device__ float g_qk [(size_t)BHN * T * DH];
__device__ float g_v  [(size_t)BHN * T * DH];
__device__ int   g_st [BHN * NH * T];
__device__ float g_inv_norm[(size_t)BHN * T];
__device__ float g_o  [(size_t)BHN * NH * T * DH];
__device__ float g_lse[BHN * NH * T];
__device__ float g_ctx[(size_t)4 * T * DM];

extern __shared__ float smem[];

// ---------------- packed fp32x2 helpers ----------------
__device__ __forceinline__ unsigned long long bcast2(float x) {
    unsigned long long r; asm("mov.b64 %0, {%1, %1};" : "=l"(r) : "f"(x)); return r;
}
__device__ __forceinline__ float2 unpk2(unsigned long long v) {
    float2 f; asm("mov.b64 {%0, %1}, %2;" : "=f"(f.x), "=f"(f.y) : "l"(v)); return f;
}
#define FMA2(d, a, b) asm("fma.rn.f32x2 %0, %1, %2, %0;" : "+l"(d) : "l"(a), "l"(b))

// ---------------- bf16 pack helpers ----------------
__device__ __forceinline__ uint32_t pkbf(float x, float y) {
    __nv_bfloat162 h = __float22bfloat162_rn(make_float2(x, y));
    return *(uint32_t*)&h;
}
__device__ __forceinline__ float2 upbf(uint32_t u) {
    __nv_bfloat162 h = *(__nv_bfloat162*)&u;
    return __bfloat1622float2(h);
}

#define MMA_BF16(c, a, b)                                                         \
    asm volatile("mma.sync.aligned.m16n8k16.row.col.f32.bf16.bf16.f32 "           \
                 "{%0,%1,%2,%3},{%4,%5,%6,%7},{%8,%9},{%0,%1,%2,%3};"             \
                 : "+f"(c[0]), "+f"(c[1]), "+f"(c[2]), "+f"(c[3])                 \
                 : "r"(a[0]), "r"(a[1]), "r"(a[2]), "r"(a[3]), "r"(b[0]), "r"(b[1]))

// ---------------- fp32 GEMM (W_qk: exact, feeds hash argmax) ----------------
__global__ __launch_bounds__(256)
void gemm_qk_kernel(const float* __restrict__ A,
                    const float* __restrict__ Bm)
{
    const int N = 512, K = 512;
    __shared__ float As[2][16][132];
    __shared__ float Bs[2][16][68];

    int tid = threadIdx.x;
    int tx = tid & 15, ty = tid >> 4;
    int bm = blockIdx.y * 128, bn = blockIdx.x * 64;

    int f0 = tid * 2, f1 = tid * 2 + 1;
    int a_row0 = f0 >> 2, a_k0 = (f0 & 3) << 2;
    int a_row1 = f1 >> 2, a_k1 = (f1 & 3) << 2;
    int b_k = tid >> 4, b_n = (tid & 15) << 2;

    float4 ar0, ar1, br;
    unsigned long long acc2[8][2];
    #pragma unroll
    for (int i = 0; i < 8; i++) { acc2[i][0] = 0ull; acc2[i][1] = 0ull; }

#define LDG_TILE(k0)                                                              \
    {   ar0 = *(const float4*)&A[(size_t)(bm + a_row0) * K + (k0) + a_k0];        \
        ar1 = *(const float4*)&A[(size_t)(bm + a_row1) * K + (k0) + a_k1];        \
        br  = *(const float4*)&Bm[(size_t)((k0) + b_k) * N + bn + b_n]; }
#define STS_TILE(buf)                                                             \
    {   As[buf][a_k0 + 0][a_row0] = ar0.x; As[buf][a_k0 + 1][a_row0] = ar0.y;     \
        As[buf][a_k0 + 2][a_row0] = ar0.z; As[buf][a_k0 + 3][a_row0] = ar0.w;     \
        As[buf][a_k1 + 0][a_row1] = ar1.x; As[buf][a_k1 + 1][a_row1] = ar1.y;     \
        As[buf][a_k1 + 2][a_row1] = ar1.z; As[buf][a_k1 + 3][a_row1] = ar1.w;     \
        *(float4*)&Bs[buf][b_k][b_n] = br; }

    LDG_TILE(0); STS_TILE(0); __syncthreads();

    const int NST = K / 16;
    for (int s = 0; s < NST; s++) {
        if (s + 1 < NST) LDG_TILE((s + 1) * 16);
        int buf = s & 1;
        #pragma unroll
        for (int k = 0; k < 16; k++) {
            float4 a0 = *(const float4*)&As[buf][k][ty * 8];
            float4 a1 = *(const float4*)&As[buf][k][ty * 8 + 4];
            ulonglong2 b2 = *(const ulonglong2*)&Bs[buf][k][tx * 4];
            float av[8] = {a0.x, a0.y, a0.z, a0.w, a1.x, a1.y, a1.z, a1.w};
            #pragma unroll
            for (int i = 0; i < 8; i++) {
                unsigned long long ap = bcast2(av[i]);
                FMA2(acc2[i][0], ap, b2.x);
                FMA2(acc2[i][1], ap, b2.y);
            }
        }
        if (s + 1 < NST) STS_TILE((s + 1) & 1);
        __syncthreads();
    }

    #pragma unroll
    for (int i = 0; i < 8; i++) {
        int m = bm + ty * 8 + i;
        float2 p0 = unpk2(acc2[i][0]), p1 = unpk2(acc2[i][1]);
        float vv[4] = {p0.x, p0.y, p1.x, p1.y};
        #pragma unroll
        for (int j = 0; j < 4; j++) {
            int n = bn + tx * 4 + j;
            int b = m >> 12, t = m & 4095;
            int h = n >> 6,  d = n & 63;
            g_qk[(((size_t)(b * 8 + h)) * T + t) * DH + d] = vv[j];
        }
    }
#undef LDG_TILE
#undef STS_TILE
}

// ======== bf16 2-split mma.sync GEMM (W_v merged / W_out + bias) ========
#define PA 36
#define PB 136
#define AW (128 * PA)
#define BW (32 * PB)
#define SMEM_BF (2 * (AW + BW) * 4)

template <int MODE>   // 1: -> g_v merged ; 2: A=g_ctx, C = acc + bias
__global__ __launch_bounds__(256)
void gemm_bf16_kernel(const float* __restrict__ A, const float* __restrict__ W,
                      const float* __restrict__ bias, float* __restrict__ Cout)
{
    uint32_t* sA0 = (uint32_t*)smem;
    uint32_t* sA1 = sA0 + AW;
    uint32_t* sB0 = sA1 + AW;
    uint32_t* sB1 = sB0 + BW;

    int tid = threadIdx.x, lane = tid & 31, wid = tid >> 5;
    int g = lane >> 2, tq = lane & 3;
    int wm = wid >> 1, wn = wid & 1;
    int m0 = wm * 32, n0 = wn * 64;
    int bm = blockIdx.y * 128, bn = blockIdx.x * 128;
    const float* Ap = (MODE == 2) ? g_ctx : A;

    float acc[2][8][4] = {};

    for (int c = 0; c < 8; c++) {
        int k0 = c * 64;
        if (c > 0) __syncthreads();

        {
            int p = lane;
            #pragma unroll 4
            for (int rr = 0; rr < 16; rr++) {
                int row = wid * 16 + rr;
                float2 av = *(const float2*)&Ap[(size_t)(bm + row) * 512 + k0 + 2 * p];
                uint32_t h0 = pkbf(av.x, av.y);
                sA0[row * PA + p] = h0;
                float2 f0 = upbf(h0);
                sA1[row * PA + p] = pkbf(av.x - f0.x, av.y - f0.y);
            }
        }
        {
            int q = lane;
            #pragma unroll
            for (int j = 0; j < 4; j++) {
                int k2 = wid * 4 + j;
                const float* w0p = &W[(size_t)(k0 + 2 * k2) * 512 + bn];
                const float* w1p = &W[(size_t)(k0 + 2 * k2 + 1) * 512 + bn];
                #pragma unroll
                for (int u = 0; u < 4; u++) {
                    int n = q + 32 * u;
                    uint32_t h0 = pkbf(w0p[n], w1p[n]);
                    sB0[k2 * PB + n] = h0;
                    float2 f0 = upbf(h0);
                    sB1[k2 * PB + n] = pkbf(w0p[n] - f0.x, w1p[n] - f0.y);
                }
            }
        }
        __syncthreads();

        #pragma unroll
        for (int ks = 0; ks < 4; ks++) {
            int kk = tq + 8 * ks;
            uint32_t ah[2][4], al[2][4];
            #pragma unroll
            for (int mi = 0; mi < 2; mi++) {
                int r0 = (m0 + mi * 16 + g) * PA;
                int r1 = (m0 + mi * 16 + g + 8) * PA;
                ah[mi][0] = sA0[r0 + kk];     ah[mi][1] = sA0[r1 + kk];
                ah[mi][2] = sA0[r0 + kk + 4]; ah[mi][3] = sA0[r1 + kk + 4];
                al[mi][0] = sA1[r0 + kk];     al[mi][1] = sA1[r1 + kk];
                al[mi][2] = sA1[r0 + kk + 4]; al[mi][3] = sA1[r1 + kk + 4];
            }
            #pragma unroll
            for (int ni = 0; ni < 8; ni++) {
                int n = n0 + ni * 8 + g;
                uint32_t bhv[2], blv[2];
                bhv[0] = sB0[kk * PB + n]; bhv[1] = sB0[(kk + 4) * PB + n];
                blv[0] = sB1[kk * PB + n]; blv[1] = sB1[(kk + 4) * PB + n];
                #pragma unroll
                for (int mi = 0; mi < 2; mi++) {
                    MMA_BF16(acc[mi][ni], ah[mi], bhv);
                    MMA_BF16(acc[mi][ni], ah[mi], blv);
                    MMA_BF16(acc[mi][ni], al[mi], bhv);
                }
            }
        }
    }

    #pragma unroll
    for (int mi = 0; mi < 2; mi++) {
        int m_top = bm + m0 + mi * 16 + g;
        #pragma unroll
        for (int ni = 0; ni < 8; ni++) {
            int n = bn + n0 + ni * 8 + 2 * tq;
            float c0 = acc[mi][ni][0], c1 = acc[mi][ni][1];
            float c2 = acc[mi][ni][2], c3 = acc[mi][ni][3];
            if (MODE == 2) {
                float2 bi2 = *(const float2*)&bias[n];
                *(float2*)&Cout[(size_t)m_top * 512 + n]       = make_float2(c0 + bi2.x, c1 + bi2.y);
                *(float2*)&Cout[(size_t)(m_top + 8) * 512 + n] = make_float2(c2 + bi2.x, c3 + bi2.y);
            } else {
                int h = n >> 6, d = n & 63;
                {
                    int b = m_top >> 12, tp = m_top & 4095;
                    *(float2*)&g_v[(((size_t)(b * 8 + h)) * T + tp) * DH + d] = make_float2(c0, c1);
                }
                {
                    int m2 = m_top + 8;
                    int b = m2 >> 12, tp = m2 & 4095;
                    *(float2*)&g_v[(((size_t)(b * 8 + h)) * T + tp) * DH + d] = make_float2(c2, c3);
                }
            }
        }
    }
}

// ======== hash + stable counting sort (+ key-norm precompute) ========
__global__ void hash_sort_kernel(const float* __restrict__ rotations)
{
    int bh = blockIdx.x >> 2, r = blockIdx.x & 3;
    __shared__ float rot[64][32];
    __shared__ unsigned char bucket[T];
    __shared__ int hist4[4][NB], offs[NB], tot[NB];
    int tid = threadIdx.x;
    for (int x = tid; x < 64 * 32; x += 256) {
        int d = x >> 5, i = x & 31;
        rot[d][i] = rotations[(d * NH + r) * 32 + i];
    }
    ((int*)hist4)[tid] = 0;
    __syncthreads();
    const float* qkbh = g_qk + (size_t)bh * T * DH;
    for (int t = tid; t < T; t += 256) {
        const float* q = qkbh + (size_t)t * DH;
        float s[32];
        float ss = 0.f;
        #pragma unroll
        for (int i = 0; i < 32; i++) s[i] = 0.f;
        for (int d4 = 0; d4 < 16; d4++) {
            float4 qv = *(const float4*)&q[d4 * 4];
            ss = fmaf(qv.x, qv.x, ss); ss = fmaf(qv.y, qv.y, ss);
            ss = fmaf(qv.z, qv.z, ss); ss = fmaf(qv.w, qv.w, ss);
            #pragma unroll
            for (int i = 0; i < 32; i++) {
                s[i] = fmaf(qv.x, rot[d4 * 4 + 0][i], s[i]);
                s[i] = fmaf(qv.y, rot[d4 * 4 + 1][i], s[i]);
                s[i] = fmaf(qv.z, rot[d4 * 4 + 2][i], s[i]);
                s[i] = fmaf(qv.w, rot[d4 * 4 + 3][i], s[i]);
            }
        }
        if (r == 0)
            g_inv_norm[(size_t)bh * T + t] = 1.0f / fmaxf(sqrtf(ss), 1e-12f);
        float best = -3.4e38f; int bi = 0;
        #pragma unroll
        for (int i = 0; i < 32; i++) { if (s[i] > best) { best = s[i]; bi = i; } }
        #pragma unroll
        for (int i = 0; i < 32; i++) { float v = -s[i]; if (v > best) { best = v; bi = 32 + i; } }
        bucket[t] = (unsigned char)bi;
        atomicAdd(&hist4[t >> 10][bi], 1);
    }
    __syncthreads();
    if (tid < NB)
        tot[tid] = hist4[0][tid] + hist4[1][tid] + hist4[2][tid] + hist4[3][tid];
    __syncthreads();
    if (tid == 0) {
        int run = 0;
        for (int b = 0; b < NB; b++) { offs[b] = run; run += tot[b]; }
    }
    __syncthreads();
    {
        int b = tid & 63, q = tid >> 6;
        int o = offs[b];
        #pragma unroll
        for (int qq = 0; qq < 3; qq++) if (qq < q) o += hist4[qq][b];
        int* stout = g_st + (bh * NH + r) * T;
        int t0 = q << 10;
        for (int t = t0; t < t0 + 1024; t++)
            if (bucket[t] == (unsigned char)b) stout[o++] = t;
    }
}

// ======== attention via bf16 mma 2-split (no overlay, single compute sync) ========
// KbH/KbL: [128 rows][36 words]; VtH/VtL: [64 d][68 words]; inv_norm 128; kpos 128
#define SMEM_ATTN2 ((2 * 128 * 36 + 2 * 64 * 68 + 256) * 4)

__global__ __launch_bounds__(128, 3)
void lsh_attn_mma_kernel()
{
    uint32_t* KbH = (uint32_t*)smem;
    uint32_t* KbL = KbH + 128 * 36;
    uint32_t* VtH = KbL + 128 * 36;
    uint32_t* VtL = VtH + 64 * 68;
    float* inv_norm = (float*)(VtL + 64 * 68);
    int*   kpos     = (int*)(inv_norm + 128);

    int tid = threadIdx.x, lane = tid & 31, warp = tid >> 5;
    int g = lane >> 2, tq = lane & 3;
    int bh = blockIdx.x >> 8, c = blockIdx.x & 255;
    int r = c >> 6, pc = (c + 255) & 255;

    {
        int gi = (tid < 64) ? (c * 64 + tid) : (pc * 64 + tid - 64);
        int p = g_st[bh * (NH * T) + gi];
        kpos[tid] = p;
        inv_norm[tid] = g_inv_norm[(size_t)bh * T + p];
    }
    __syncthreads();

    // ---- K gather: warp w rows 32w..32w+31; lane = k-pair word
    for (int rr = 0; rr < 32; rr++) {
        int row = warp * 32 + rr;
        float2 f2 = ((const float2*)(g_qk + ((size_t)bh * T + kpos[row]) * DH))[lane];
        uint32_t hw = pkbf(f2.x, f2.y);
        KbH[row * 36 + lane] = hw;
        float2 hf = upbf(hw);
        KbL[row * 36 + lane] = pkbf(f2.x - hf.x, f2.y - hf.y);
    }
    // ---- V gather transposed (immediately; independent of K)
    for (int i = 0; i < 16; i++) {
        int k2v = warp * 16 + i;
        const float* va = g_v + ((size_t)bh * T + kpos[2 * k2v]) * DH;
        const float* vb = g_v + ((size_t)bh * T + kpos[2 * k2v + 1]) * DH;
        #pragma unroll
        for (int h2 = 0; h2 < 2; h2++) {
            int d = lane + 32 * h2;
            float2 f2 = make_float2(va[d], vb[d]);
            uint32_t hw = pkbf(f2.x, f2.y);
            VtH[d * 68 + k2v] = hw;
            float2 hf = upbf(hw);
            VtL[d * 68 + k2v] = pkbf(f2.x - hf.x, f2.y - hf.y);
        }
    }
    __syncthreads();   // single compute barrier

    // ---- QK^T: warp w -> rows m0..m0+15, all 128 cols (16 n8-tiles)
    int m0 = warp * 16;
    float acc[16][4];
    #pragma unroll
    for (int j = 0; j < 16; j++)
        #pragma unroll
        for (int x = 0; x < 4; x++) acc[j][x] = 0.f;

    int ra = (m0 + g) * 36, rb = (m0 + g + 8) * 36;
    #pragma unroll
    for (int kt = 0; kt < 4; kt++) {
        int kw = kt * 8 + tq;
        uint32_t ah[4] = {KbH[ra + kw], KbH[rb + kw], KbH[ra + kw + 4], KbH[rb + kw + 4]};
        uint32_t al[4] = {KbL[ra + kw], KbL[rb + kw], KbL[ra + kw + 4], KbL[rb + kw + 4]};
        #pragma unroll
        for (int j = 0; j < 16; j++) {
            int bn = (8 * j + g) * 36;
            uint32_t bhv[2] = {KbH[bn + kw], KbH[bn + kw + 4]};
            uint32_t blv[2] = {KbL[bn + kw], KbL[bn + kw + 4]};
            MMA_BF16(acc[j], ah, bhv);
            MMA_BF16(acc[j], ah, blv);
            MMA_BF16(acc[j], al, bhv);
        }
    }

    // ---- scale + self-mask
    int r0 = m0 + g, r1 = r0 + 8;
    int qp0 = kpos[r0], qp1 = kpos[r1];
    #pragma unroll
    for (int j = 0; j < 16; j++) {
        int n = 8 * j + 2 * tq;
        float in0 = inv_norm[n], in1 = inv_norm[n + 1];
        int kc0 = kpos[n], kc1 = kpos[n + 1];
        acc[j][0] = (kc0 == qp0) ? SELF_VAL : acc[j][0] * in0 * 0.125f;
        acc[j][1] = (kc1 == qp0) ? SELF_VAL : acc[j][1] * in1 * 0.125f;
        acc[j][2] = (kc0 == qp1) ? SELF_VAL : acc[j][2] * in0 * 0.125f;
        acc[j][3] = (kc1 == qp1) ? SELF_VAL : acc[j][3] * in1 * 0.125f;
    }

    // ---- softmax on fragments (quad shfl)
    float mA = -3.4e38f, mB = -3.4e38f;
    #pragma unroll
    for (int j = 0; j < 16; j++) {
        mA = fmaxf(mA, fmaxf(acc[j][0], acc[j][1]));
        mB = fmaxf(mB, fmaxf(acc[j][2], acc[j][3]));
    }
    mA = fmaxf(mA, __shfl_xor_sync(0xffffffffu, mA, 1));
    mA = fmaxf(mA, __shfl_xor_sync(0xffffffffu, mA, 2));
    mB = fmaxf(mB, __shfl_xor_sync(0xffffffffu, mB, 1));
    mB = fmaxf(mB, __shfl_xor_sync(0xffffffffu, mB, 2));
    float sA = 0.f, sB = 0.f;
    #pragma unroll
    for (int j = 0; j < 16; j++) {
        acc[j][0] = __expf(acc[j][0] - mA); sA += acc[j][0];
        acc[j][1] = __expf(acc[j][1] - mA); sA += acc[j][1];
        acc[j][2] = __expf(acc[j][2] - mB); sB += acc[j][2];
        acc[j][3] = __expf(acc[j][3] - mB); sB += acc[j][3];
    }
    sA += __shfl_xor_sync(0xffffffffu, sA, 1);
    sA += __shfl_xor_sync(0xffffffffu, sA, 2);
    sB += __shfl_xor_sync(0xffffffffu, sB, 1);
    sB += __shfl_xor_sync(0xffffffffu, sB, 2);
    if (tq == 0) {
        size_t lb = ((size_t)bh * NH + r) * T;
        g_lse[lb + qp0] = mA + logf(sA);
        g_lse[lb + qp1] = mB + logf(sB);
    }
    float invA = 1.0f / sA, invB = 1.0f / sB;

    // ---- P -> A-fragments (register repack)
    uint32_t Ph[8][4], Pl[8][4];
    #pragma unroll
    for (int kt2 = 0; kt2 < 8; kt2++) {
        int j0 = 2 * kt2, j1 = 2 * kt2 + 1;
        Ph[kt2][0] = pkbf(acc[j0][0], acc[j0][1]);
        Ph[kt2][1] = pkbf(acc[j0][2], acc[j0][3]);
        Ph[kt2][2] = pkbf(acc[j1][0], acc[j1][1]);
        Ph[kt2][3] = pkbf(acc[j1][2], acc[j1][3]);
        float2 f;
        f = upbf(Ph[kt2][0]); Pl[kt2][0] = pkbf(acc[j0][0] - f.x, acc[j0][1] - f.y);
        f = upbf(Ph[kt2][1]); Pl[kt2][1] = pkbf(acc[j0][2] - f.x, acc[j0][3] - f.y);
        f = upbf(Ph[kt2][2]); Pl[kt2][2] = pkbf(acc[j1][0] - f.x, acc[j1][1] - f.y);
        f = upbf(Ph[kt2][3]); Pl[kt2][3] = pkbf(acc[j1][2] - f.x, acc[j1][3] - f.y);
    }

    // ---- PV
    float oacc[8][4];
    #pragma unroll
    for (int j = 0; j < 8; j++)
        #pragma unroll
        for (int x = 0; x < 4; x++) oacc[j][x] = 0.f;

    #pragma unroll
    for (int kt2 = 0; kt2 < 8; kt2++) {
        int kw = kt2 * 8 + tq;
        #pragma unroll
        for (int j2 = 0; j2 < 8; j2++) {
            int vn = (8 * j2 + g) * 68;
            uint32_t bhv[2] = {VtH[vn + kw], VtH[vn + kw + 4]};
            uint32_t blv[2] = {VtL[vn + kw], VtL[vn + kw + 4]};
            MMA_BF16(oacc[j2], Ph[kt2], bhv);
            MMA_BF16(oacc[j2], Ph[kt2], blv);
            MMA_BF16(oacc[j2], Pl[kt2], bhv);
        }
    }

    // ---- epilogue
    {
        size_t lb = ((size_t)bh * NH + r) * T;
        size_t b0 = (lb + qp0) * DH;
        size_t b1 = (lb + qp1) * DH;
        #pragma unroll
        for (int j2 = 0; j2 < 8; j2++) {
            int d0 = 8 * j2 + 2 * tq;
            *(float2*)&g_o[b0 + d0] = make_float2(oacc[j2][0] * invA, oacc[j2][1] * invA);
            *(float2*)&g_o[b1 + d0] = make_float2(oacc[j2][2] * invB, oacc[j2][3] * invB);
        }
    }
}

// ======== combine ========
__global__ void combine_kernel()
{
    int idx = blockIdx.x * 256 + threadIdx.x;
    int d = idx & 63, pos = (idx >> 6) & 4095, bh = idx >> 18;
    float l[4];
    #pragma unroll
    for (int r = 0; r < 4; r++) l[r] = g_lse[((size_t)bh * 4 + r) * T + pos];
    float m = fmaxf(fmaxf(l[0], l[1]), fmaxf(l[2], l[3]));
    float w[4], ws = 0.f;
    #pragma unroll
    for (int r = 0; r < 4; r++) { w[r] = __expf(l[r] - m); ws += w[r]; }
    float o = 0.f;
    #pragma unroll
    for (int r = 0; r < 4; r++)
        o += w[r] * g_o[(((size_t)bh * 4 + r) * T + pos) * DH + d];
    o /= ws;
    int b = bh >> 3, h = bh & 7;
    g_ctx[((size_t)b * T + pos) * DM + h * 64 + d] = o;
}

// ======== launch ========
extern "C" void kernel_launch(void* const* d_in, const int* in_sizes, int n_in,
                              void* d_out, int out_size)
{
    (void)in_sizes; (void)n_in; (void)out_size;
    const float* queries   = (const float*)d_in[0];
    const float* W_qk      = (const float*)d_in[3];
    const float* W_v       = (const float*)d_in[4];
    const float* W_out     = (const float*)d_in[5];
    const float* b_out     = (const float*)d_in[6];
    const float* rotations = (const float*)d_in[7];
    float* out = (float*)d_out;

    static cudaStream_t s_aux = nullptr;
    static cudaEvent_t ev_fork = nullptr, ev_join = nullptr;
    if (!s_aux) {
        cudaStreamCreateWithFlags(&s_aux, cudaStreamNonBlocking);
        cudaEventCreateWithFlags(&ev_fork, cudaEventDisableTiming);
        cudaEventCreateWithFlags(&ev_join, cudaEventDisableTiming);
    }

    dim3 gq(512 / 64, 16384 / 128);
    dim3 gb(512 / 128, 16384 / 128);

    cudaFuncSetAttribute(gemm_bf16_kernel<1>, cudaFuncAttributeMaxDynamicSharedMemorySize, SMEM_BF);
    cudaFuncSetAttribute(gemm_bf16_kernel<2>, cudaFuncAttributeMaxDynamicSharedMemorySize, SMEM_BF);
    cudaFuncSetAttribute(lsh_attn_mma_kernel, cudaFuncAttributeMaxDynamicSharedMemorySize, SMEM_ATTN2);

    cudaEventRecord(ev_fork, 0);
    cudaStreamWaitEvent(s_aux, ev_fork, 0);
    gemm_bf16_kernel<1><<<gb, 256, SMEM_BF, s_aux>>>(queries, W_v, nullptr, nullptr);
    cudaEventRecord(ev_join, s_aux);

    gemm_qk_kernel<<<gq, 256>>>(queries, W_qk);
    hash_sort_kernel<<<BHN * NH, 256>>>(rotations);

    cudaStreamWaitEvent(0, ev_join, 0);

    lsh_attn_mma_kernel<<<BHN * 256, 128, SMEM_ATTN2>>>();

    combine_kernel<<<(BHN * T * DH) / 256, 256>>>();

    gemm_bf16_kernel<2><<<gb, 256, SMEM_BF>>>(nullptr, W_out, b_out, out);
}

// round 12
// speedup vs baseline: 2.0623x; 1.1551x over previous
#include <cuda_runtime.h>
#include <cuda_bf16.h>
#include <math.h>
#include <stdint.h>

#define T      4096
#define DH     64
#define NH     4
#define NB     64
#define DM     512
#define BHN    32
#define SELF_VAL (-5e4f)

__device__ float g_qk [(size_t)BHN * T * DH];
__device__ float g_v  [(size_t)BHN * T * DH];
__device__ int   g_st [BHN * NH * T];
__device__ float g_inv_norm[(size_t)BHN * T];
__device__ float g_o  [(size_t)BHN * NH * T * DH];
__device__ float g_lse[BHN * NH * T];
__device__ float g_ctx[(size_t)4 * T * DM];

extern __shared__ float smem[];

// ---------------- packed fp32x2 helpers ----------------
__device__ __forceinline__ unsigned long long bcast2(float x) {
    unsigned long long r; asm("mov.b64 %0, {%1, %1};" : "=l"(r) : "f"(x)); return r;
}
__device__ __forceinline__ float2 unpk2(unsigned long long v) {
    float2 f; asm("mov.b64 {%0, %1}, %2;" : "=f"(f.x), "=f"(f.y) : "l"(v)); return f;
}
#define FMA2(d, a, b) asm("fma.rn.f32x2 %0, %1, %2, %0;" : "+l"(d) : "l"(a), "l"(b))

// ---------------- bf16 pack helpers ----------------
__device__ __forceinline__ uint32_t pkbf(float x, float y) {
    __nv_bfloat162 h = __float22bfloat162_rn(make_float2(x, y));
    return *(uint32_t*)&h;
}
__device__ __forceinline__ float2 upbf(uint32_t u) {
    __nv_bfloat162 h = *(__nv_bfloat162*)&u;
    return __bfloat1622float2(h);
}

#define MMA_BF16(c, a, b)                                                         \
    asm volatile("mma.sync.aligned.m16n8k16.row.col.f32.bf16.bf16.f32 "           \
                 "{%0,%1,%2,%3},{%4,%5,%6,%7},{%8,%9},{%0,%1,%2,%3};"             \
                 : "+f"(c[0]), "+f"(c[1]), "+f"(c[2]), "+f"(c[3])                 \
                 : "r"(a[0]), "r"(a[1]), "r"(a[2]), "r"(a[3]), "r"(b[0]), "r"(b[1]))

// ---------------- fp32 GEMM (W_qk: exact, feeds hash argmax) ----------------
__global__ __launch_bounds__(256)
void gemm_qk_kernel(const float* __restrict__ A,
                    const float* __restrict__ Bm)
{
    const int N = 512, K = 512;
    __shared__ float As[2][16][132];
    __shared__ float Bs[2][16][68];

    int tid = threadIdx.x;
    int tx = tid & 15, ty = tid >> 4;
    int bm = blockIdx.y * 128, bn = blockIdx.x * 64;

    int f0 = tid * 2, f1 = tid * 2 + 1;
    int a_row0 = f0 >> 2, a_k0 = (f0 & 3) << 2;
    int a_row1 = f1 >> 2, a_k1 = (f1 & 3) << 2;
    int b_k = tid >> 4, b_n = (tid & 15) << 2;

    float4 ar0, ar1, br;
    unsigned long long acc2[8][2];
    #pragma unroll
    for (int i = 0; i < 8; i++) { acc2[i][0] = 0ull; acc2[i][1] = 0ull; }

#define LDG_TILE(k0)                                                              \
    {   ar0 = *(const float4*)&A[(size_t)(bm + a_row0) * K + (k0) + a_k0];        \
        ar1 = *(const float4*)&A[(size_t)(bm + a_row1) * K + (k0) + a_k1];        \
        br  = *(const float4*)&Bm[(size_t)((k0) + b_k) * N + bn + b_n]; }
#define STS_TILE(buf)                                                             \
    {   As[buf][a_k0 + 0][a_row0] = ar0.x; As[buf][a_k0 + 1][a_row0] = ar0.y;     \
        As[buf][a_k0 + 2][a_row0] = ar0.z; As[buf][a_k0 + 3][a_row0] = ar0.w;     \
        As[buf][a_k1 + 0][a_row1] = ar1.x; As[buf][a_k1 + 1][a_row1] = ar1.y;     \
        As[buf][a_k1 + 2][a_row1] = ar1.z; As[buf][a_k1 + 3][a_row1] = ar1.w;     \
        *(float4*)&Bs[buf][b_k][b_n] = br; }

    LDG_TILE(0); STS_TILE(0); __syncthreads();

    const int NST = K / 16;
    for (int s = 0; s < NST; s++) {
        if (s + 1 < NST) LDG_TILE((s + 1) * 16);
        int buf = s & 1;
        #pragma unroll
        for (int k = 0; k < 16; k++) {
            float4 a0 = *(const float4*)&As[buf][k][ty * 8];
            float4 a1 = *(const float4*)&As[buf][k][ty * 8 + 4];
            ulonglong2 b2 = *(const ulonglong2*)&Bs[buf][k][tx * 4];
            float av[8] = {a0.x, a0.y, a0.z, a0.w, a1.x, a1.y, a1.z, a1.w};
            #pragma unroll
            for (int i = 0; i < 8; i++) {
                unsigned long long ap = bcast2(av[i]);
                FMA2(acc2[i][0], ap, b2.x);
                FMA2(acc2[i][1], ap, b2.y);
            }
        }
        if (s + 1 < NST) STS_TILE((s + 1) & 1);
        __syncthreads();
    }

    #pragma unroll
    for (int i = 0; i < 8; i++) {
        int m = bm + ty * 8 + i;
        float2 p0 = unpk2(acc2[i][0]), p1 = unpk2(acc2[i][1]);
        float vv[4] = {p0.x, p0.y, p1.x, p1.y};
        #pragma unroll
        for (int j = 0; j < 4; j++) {
            int n = bn + tx * 4 + j;
            int b = m >> 12, t = m & 4095;
            int h = n >> 6,  d = n & 63;
            g_qk[(((size_t)(b * 8 + h)) * T + t) * DH + d] = vv[j];
        }
    }
#undef LDG_TILE
#undef STS_TILE
}

// ======== bf16 2-split mma.sync GEMM (W_v merged / W_out + bias) ========
#define PA 36
#define PB 136
#define AW (128 * PA)
#define BW (32 * PB)
#define SMEM_BF (2 * (AW + BW) * 4)

template <int MODE>   // 1: -> g_v merged ; 2: A=g_ctx, C = acc + bias
__global__ __launch_bounds__(256)
void gemm_bf16_kernel(const float* __restrict__ A, const float* __restrict__ W,
                      const float* __restrict__ bias, float* __restrict__ Cout)
{
    uint32_t* sA0 = (uint32_t*)smem;
    uint32_t* sA1 = sA0 + AW;
    uint32_t* sB0 = sA1 + AW;
    uint32_t* sB1 = sB0 + BW;

    int tid = threadIdx.x, lane = tid & 31, wid = tid >> 5;
    int g = lane >> 2, tq = lane & 3;
    int wm = wid >> 1, wn = wid & 1;
    int m0 = wm * 32, n0 = wn * 64;
    int bm = blockIdx.y * 128, bn = blockIdx.x * 128;
    const float* Ap = (MODE == 2) ? g_ctx : A;

    float acc[2][8][4] = {};

    for (int c = 0; c < 8; c++) {
        int k0 = c * 64;
        if (c > 0) __syncthreads();

        {
            int p = lane;
            #pragma unroll 4
            for (int rr = 0; rr < 16; rr++) {
                int row = wid * 16 + rr;
                float2 av = *(const float2*)&Ap[(size_t)(bm + row) * 512 + k0 + 2 * p];
                uint32_t h0 = pkbf(av.x, av.y);
                sA0[row * PA + p] = h0;
                float2 f0 = upbf(h0);
                sA1[row * PA + p] = pkbf(av.x - f0.x, av.y - f0.y);
            }
        }
        {
            int q = lane;
            #pragma unroll
            for (int j = 0; j < 4; j++) {
                int k2 = wid * 4 + j;
                const float* w0p = &W[(size_t)(k0 + 2 * k2) * 512 + bn];
                const float* w1p = &W[(size_t)(k0 + 2 * k2 + 1) * 512 + bn];
                #pragma unroll
                for (int u = 0; u < 4; u++) {
                    int n = q + 32 * u;
                    uint32_t h0 = pkbf(w0p[n], w1p[n]);
                    sB0[k2 * PB + n] = h0;
                    float2 f0 = upbf(h0);
                    sB1[k2 * PB + n] = pkbf(w0p[n] - f0.x, w1p[n] - f0.y);
                }
            }
        }
        __syncthreads();

        #pragma unroll
        for (int ks = 0; ks < 4; ks++) {
            int kk = tq + 8 * ks;
            uint32_t ah[2][4], al[2][4];
            #pragma unroll
            for (int mi = 0; mi < 2; mi++) {
                int r0 = (m0 + mi * 16 + g) * PA;
                int r1 = (m0 + mi * 16 + g + 8) * PA;
                ah[mi][0] = sA0[r0 + kk];     ah[mi][1] = sA0[r1 + kk];
                ah[mi][2] = sA0[r0 + kk + 4]; ah[mi][3] = sA0[r1 + kk + 4];
                al[mi][0] = sA1[r0 + kk];     al[mi][1] = sA1[r1 + kk];
                al[mi][2] = sA1[r0 + kk + 4]; al[mi][3] = sA1[r1 + kk + 4];
            }
            #pragma unroll
            for (int ni = 0; ni < 8; ni++) {
                int n = n0 + ni * 8 + g;
                uint32_t bhv[2], blv[2];
                bhv[0] = sB0[kk * PB + n]; bhv[1] = sB0[(kk + 4) * PB + n];
                blv[0] = sB1[kk * PB + n]; blv[1] = sB1[(kk + 4) * PB + n];
                #pragma unroll
                for (int mi = 0; mi < 2; mi++) {
                    MMA_BF16(acc[mi][ni], ah[mi], bhv);
                    MMA_BF16(acc[mi][ni], ah[mi], blv);
                    MMA_BF16(acc[mi][ni], al[mi], bhv);
                }
            }
        }
    }

    #pragma unroll
    for (int mi = 0; mi < 2; mi++) {
        int m_top = bm + m0 + mi * 16 + g;
        #pragma unroll
        for (int ni = 0; ni < 8; ni++) {
            int n = bn + n0 + ni * 8 + 2 * tq;
            float c0 = acc[mi][ni][0], c1 = acc[mi][ni][1];
            float c2 = acc[mi][ni][2], c3 = acc[mi][ni][3];
            if (MODE == 2) {
                float2 bi2 = *(const float2*)&bias[n];
                *(float2*)&Cout[(size_t)m_top * 512 + n]       = make_float2(c0 + bi2.x, c1 + bi2.y);
                *(float2*)&Cout[(size_t)(m_top + 8) * 512 + n] = make_float2(c2 + bi2.x, c3 + bi2.y);
            } else {
                int h = n >> 6, d = n & 63;
                {
                    int b = m_top >> 12, tp = m_top & 4095;
                    *(float2*)&g_v[(((size_t)(b * 8 + h)) * T + tp) * DH + d] = make_float2(c0, c1);
                }
                {
                    int m2 = m_top + 8;
                    int b = m2 >> 12, tp = m2 & 4095;
                    *(float2*)&g_v[(((size_t)(b * 8 + h)) * T + tp) * DH + d] = make_float2(c2, c3);
                }
            }
        }
    }
}

// ======== hash + stable counting sort (+ key-norm precompute) ========
__global__ void hash_sort_kernel(const float* __restrict__ rotations)
{
    int bh = blockIdx.x >> 2, r = blockIdx.x & 3;
    __shared__ float rot[64][32];
    __shared__ unsigned char bucket[T];
    __shared__ int hist4[4][NB], offs[NB], tot[NB];
    int tid = threadIdx.x;
    for (int x = tid; x < 64 * 32; x += 256) {
        int d = x >> 5, i = x & 31;
        rot[d][i] = rotations[(d * NH + r) * 32 + i];
    }
    ((int*)hist4)[tid] = 0;
    __syncthreads();
    const float* qkbh = g_qk + (size_t)bh * T * DH;
    for (int t = tid; t < T; t += 256) {
        const float* q = qkbh + (size_t)t * DH;
        float s[32];
        float ss = 0.f;
        #pragma unroll
        for (int i = 0; i < 32; i++) s[i] = 0.f;
        for (int d4 = 0; d4 < 16; d4++) {
            float4 qv = *(const float4*)&q[d4 * 4];
            ss = fmaf(qv.x, qv.x, ss); ss = fmaf(qv.y, qv.y, ss);
            ss = fmaf(qv.z, qv.z, ss); ss = fmaf(qv.w, qv.w, ss);
            #pragma unroll
            for (int i = 0; i < 32; i++) {
                s[i] = fmaf(qv.x, rot[d4 * 4 + 0][i], s[i]);
                s[i] = fmaf(qv.y, rot[d4 * 4 + 1][i], s[i]);
                s[i] = fmaf(qv.z, rot[d4 * 4 + 2][i], s[i]);
                s[i] = fmaf(qv.w, rot[d4 * 4 + 3][i], s[i]);
            }
        }
        if (r == 0)
            g_inv_norm[(size_t)bh * T + t] = 1.0f / fmaxf(sqrtf(ss), 1e-12f);
        float best = -3.4e38f; int bi = 0;
        #pragma unroll
        for (int i = 0; i < 32; i++) { if (s[i] > best) { best = s[i]; bi = i; } }
        #pragma unroll
        for (int i = 0; i < 32; i++) { float v = -s[i]; if (v > best) { best = v; bi = 32 + i; } }
        bucket[t] = (unsigned char)bi;
        atomicAdd(&hist4[t >> 10][bi], 1);
    }
    __syncthreads();
    if (tid < NB)
        tot[tid] = hist4[0][tid] + hist4[1][tid] + hist4[2][tid] + hist4[3][tid];
    __syncthreads();
    if (tid == 0) {
        int run = 0;
        for (int b = 0; b < NB; b++) { offs[b] = run; run += tot[b]; }
    }
    __syncthreads();
    {
        int b = tid & 63, q = tid >> 6;
        int o = offs[b];
        #pragma unroll
        for (int qq = 0; qq < 3; qq++) if (qq < q) o += hist4[qq][b];
        int* stout = g_st + (bh * NH + r) * T;
        int t0 = q << 10;
        for (int t = t0; t < t0 + 1024; t++)
            if (bucket[t] == (unsigned char)b) stout[o++] = t;
    }
}

// ======== attention via bf16 mma 2-split: 8 warps, split-column warp pairs ========
// KbH/KbL [128][36]; VtH/VtL [64][68]; inv_norm 128; kpos 128; pmax 128; psum 128
// Opart (fp32 partial O, [4 stripes][16][68]) overlays KbH after QK completes.
#define SMEM_ATTN2 ((2 * 128 * 36 + 2 * 64 * 68 + 512) * 4)

__global__ __launch_bounds__(256, 3)
void lsh_attn_mma_kernel()
{
    uint32_t* KbH = (uint32_t*)smem;
    uint32_t* KbL = KbH + 128 * 36;
    uint32_t* VtH = KbL + 128 * 36;
    uint32_t* VtL = VtH + 64 * 68;
    float* inv_norm = (float*)(VtL + 64 * 68);
    int*   kpos = (int*)(inv_norm + 128);
    float* pmax = (float*)(kpos + 128);
    float* psum = pmax + 128;
    float* Opart = (float*)KbH;     // overlay; safe after the softmax barriers

    int tid = threadIdx.x, lane = tid & 31, warp = tid >> 5;
    int g = lane >> 2, tq = lane & 3;
    int s = warp >> 1, h = warp & 1;
    int bh = blockIdx.x >> 8, c = blockIdx.x & 255;
    int r = c >> 6, pc = (c + 255) & 255;

    if (tid < 128) {
        int gi = (tid < 64) ? (c * 64 + tid) : (pc * 64 + tid - 64);
        int p = g_st[bh * (NH * T) + gi];
        kpos[tid] = p;
        inv_norm[tid] = g_inv_norm[(size_t)bh * T + p];
    }
    __syncthreads();

    // ---- K gather: each warp 16 rows
    for (int rr = 0; rr < 16; rr++) {
        int row = warp * 16 + rr;
        float2 f2 = ((const float2*)(g_qk + ((size_t)bh * T + kpos[row]) * DH))[lane];
        uint32_t hw = pkbf(f2.x, f2.y);
        KbH[row * 36 + lane] = hw;
        float2 hf = upbf(hw);
        KbL[row * 36 + lane] = pkbf(f2.x - hf.x, f2.y - hf.y);
    }
    // ---- V gather transposed: each warp 8 row-pairs
    for (int i = 0; i < 8; i++) {
        int k2v = warp * 8 + i;
        const float* va = g_v + ((size_t)bh * T + kpos[2 * k2v]) * DH;
        const float* vb = g_v + ((size_t)bh * T + kpos[2 * k2v + 1]) * DH;
        #pragma unroll
        for (int h2 = 0; h2 < 2; h2++) {
            int d = lane + 32 * h2;
            float2 f2 = make_float2(va[d], vb[d]);
            uint32_t hw = pkbf(f2.x, f2.y);
            VtH[d * 68 + k2v] = hw;
            float2 hf = upbf(hw);
            VtL[d * 68 + k2v] = pkbf(f2.x - hf.x, f2.y - hf.y);
        }
    }
    __syncthreads();

    // ---- QK: stripe s rows 16s..+15; half h cols 64h..64h+63 (8 n8-tiles)
    int m0 = s * 16;
    float acc[8][4];
    #pragma unroll
    for (int j = 0; j < 8; j++)
        #pragma unroll
        for (int x = 0; x < 4; x++) acc[j][x] = 0.f;

    int ra = (m0 + g) * 36, rb = (m0 + g + 8) * 36;
    #pragma unroll
    for (int kt = 0; kt < 4; kt++) {
        int kw = kt * 8 + tq;
        uint32_t ah[4] = {KbH[ra + kw], KbH[rb + kw], KbH[ra + kw + 4], KbH[rb + kw + 4]};
        uint32_t al[4] = {KbL[ra + kw], KbL[rb + kw], KbL[ra + kw + 4], KbL[rb + kw + 4]};
        #pragma unroll
        for (int jj = 0; jj < 8; jj++) {
            int bn = ((8 * h + jj) * 8 + g) * 36;
            uint32_t bhv[2] = {KbH[bn + kw], KbH[bn + kw + 4]};
            uint32_t blv[2] = {KbL[bn + kw], KbL[bn + kw + 4]};
            MMA_BF16(acc[jj], ah, bhv);
            MMA_BF16(acc[jj], ah, blv);
            MMA_BF16(acc[jj], al, bhv);
        }
    }

    // ---- scale + self-mask
    int r0 = m0 + g, r1 = r0 + 8;
    int qp0 = kpos[r0], qp1 = kpos[r1];
    #pragma unroll
    for (int jj = 0; jj < 8; jj++) {
        int n = (8 * h + jj) * 8 + 2 * tq;
        float in0 = inv_norm[n], in1 = inv_norm[n + 1];
        int kc0 = kpos[n], kc1 = kpos[n + 1];
        acc[jj][0] = (kc0 == qp0) ? SELF_VAL : acc[jj][0] * in0 * 0.125f;
        acc[jj][1] = (kc1 == qp0) ? SELF_VAL : acc[jj][1] * in1 * 0.125f;
        acc[jj][2] = (kc0 == qp1) ? SELF_VAL : acc[jj][2] * in0 * 0.125f;
        acc[jj][3] = (kc1 == qp1) ? SELF_VAL : acc[jj][3] * in1 * 0.125f;
    }

    // ---- softmax: partial max (this half) -> exchange -> exp/sum -> exchange
    float mA = -3.4e38f, mB = -3.4e38f;
    #pragma unroll
    for (int jj = 0; jj < 8; jj++) {
        mA = fmaxf(mA, fmaxf(acc[jj][0], acc[jj][1]));
        mB = fmaxf(mB, fmaxf(acc[jj][2], acc[jj][3]));
    }
    mA = fmaxf(mA, __shfl_xor_sync(0xffffffffu, mA, 1));
    mA = fmaxf(mA, __shfl_xor_sync(0xffffffffu, mA, 2));
    mB = fmaxf(mB, __shfl_xor_sync(0xffffffffu, mB, 1));
    mB = fmaxf(mB, __shfl_xor_sync(0xffffffffu, mB, 2));
    if (tq == 0) {
        pmax[(s * 2 + h) * 16 + g]     = mA;
        pmax[(s * 2 + h) * 16 + g + 8] = mB;
    }
    __syncthreads();
    mA = fmaxf(mA, pmax[(s * 2 + (1 - h)) * 16 + g]);
    mB = fmaxf(mB, pmax[(s * 2 + (1 - h)) * 16 + g + 8]);

    float sA = 0.f, sB = 0.f;
    #pragma unroll
    for (int jj = 0; jj < 8; jj++) {
        acc[jj][0] = __expf(acc[jj][0] - mA); sA += acc[jj][0];
        acc[jj][1] = __expf(acc[jj][1] - mA); sA += acc[jj][1];
        acc[jj][2] = __expf(acc[jj][2] - mB); sB += acc[jj][2];
        acc[jj][3] = __expf(acc[jj][3] - mB); sB += acc[jj][3];
    }
    sA += __shfl_xor_sync(0xffffffffu, sA, 1);
    sA += __shfl_xor_sync(0xffffffffu, sA, 2);
    sB += __shfl_xor_sync(0xffffffffu, sB, 1);
    sB += __shfl_xor_sync(0xffffffffu, sB, 2);
    if (tq == 0) {
        psum[(s * 2 + h) * 16 + g]     = sA;
        psum[(s * 2 + h) * 16 + g + 8] = sB;
    }
    __syncthreads();
    sA += psum[(s * 2 + (1 - h)) * 16 + g];
    sB += psum[(s * 2 + (1 - h)) * 16 + g + 8];
    if (h == 0 && tq == 0) {
        size_t lb = ((size_t)bh * NH + r) * T;
        g_lse[lb + qp0] = mA + logf(sA);
        g_lse[lb + qp1] = mB + logf(sB);
    }
    float invA = 1.0f / sA, invB = 1.0f / sB;

    // ---- P -> A-fragments for this half's 4 k16-tiles
    uint32_t Ph[4][4], Pl[4][4];
    #pragma unroll
    for (int t2 = 0; t2 < 4; t2++) {
        int j0 = 2 * t2, j1 = 2 * t2 + 1;
        Ph[t2][0] = pkbf(acc[j0][0], acc[j0][1]);
        Ph[t2][1] = pkbf(acc[j0][2], acc[j0][3]);
        Ph[t2][2] = pkbf(acc[j1][0], acc[j1][1]);
        Ph[t2][3] = pkbf(acc[j1][2], acc[j1][3]);
        float2 f;
        f = upbf(Ph[t2][0]); Pl[t2][0] = pkbf(acc[j0][0] - f.x, acc[j0][1] - f.y);
        f = upbf(Ph[t2][1]); Pl[t2][1] = pkbf(acc[j0][2] - f.x, acc[j0][3] - f.y);
        f = upbf(Ph[t2][2]); Pl[t2][2] = pkbf(acc[j1][0] - f.x, acc[j1][1] - f.y);
        f = upbf(Ph[t2][3]); Pl[t2][3] = pkbf(acc[j1][2] - f.x, acc[j1][3] - f.y);
    }

    // ---- PV over this half's k range (4 k16-tiles), full dh
    float oacc[8][4];
    #pragma unroll
    for (int j = 0; j < 8; j++)
        #pragma unroll
        for (int x = 0; x < 4; x++) oacc[j][x] = 0.f;

    #pragma unroll
    for (int t2 = 0; t2 < 4; t2++) {
        int kw = (4 * h + t2) * 8 + tq;
        #pragma unroll
        for (int j2 = 0; j2 < 8; j2++) {
            int vn = (8 * j2 + g) * 68;
            uint32_t bhv[2] = {VtH[vn + kw], VtH[vn + kw + 4]};
            uint32_t blv[2] = {VtL[vn + kw], VtL[vn + kw + 4]};
            MMA_BF16(oacc[j2], Ph[t2], bhv);
            MMA_BF16(oacc[j2], Ph[t2], blv);
            MMA_BF16(oacc[j2], Pl[t2], bhv);
        }
    }

    // ---- combine the two halves (h0 writes partial -> h1 adds + stores)
    if (h == 0) {
        float* op = Opart + s * (16 * 68);
        #pragma unroll
        for (int j2 = 0; j2 < 8; j2++) {
            int d0 = 8 * j2 + 2 * tq;
            *(float2*)&op[g * 68 + d0]       = make_float2(oacc[j2][0], oacc[j2][1]);
            *(float2*)&op[(g + 8) * 68 + d0] = make_float2(oacc[j2][2], oacc[j2][3]);
        }
    }
    __syncthreads();
    if (h == 1) {
        float* op = Opart + s * (16 * 68);
        size_t lb = ((size_t)bh * NH + r) * T;
        size_t b0 = (lb + qp0) * DH;
        size_t b1 = (lb + qp1) * DH;
        #pragma unroll
        for (int j2 = 0; j2 < 8; j2++) {
            int d0 = 8 * j2 + 2 * tq;
            float2 pa = *(float2*)&op[g * 68 + d0];
            float2 pb = *(float2*)&op[(g + 8) * 68 + d0];
            *(float2*)&g_o[b0 + d0] = make_float2((oacc[j2][0] + pa.x) * invA,
                                                  (oacc[j2][1] + pa.y) * invA);
            *(float2*)&g_o[b1 + d0] = make_float2((oacc[j2][2] + pb.x) * invB,
                                                  (oacc[j2][3] + pb.y) * invB);
        }
    }
}

// ======== combine ========
__global__ void combine_kernel()
{
    int idx = blockIdx.x * 256 + threadIdx.x;
    int d = idx & 63, pos = (idx >> 6) & 4095, bh = idx >> 18;
    float l[4];
    #pragma unroll
    for (int r = 0; r < 4; r++) l[r] = g_lse[((size_t)bh * 4 + r) * T + pos];
    float m = fmaxf(fmaxf(l[0], l[1]), fmaxf(l[2], l[3]));
    float w[4], ws = 0.f;
    #pragma unroll
    for (int r = 0; r < 4; r++) { w[r] = __expf(l[r] - m); ws += w[r]; }
    float o = 0.f;
    #pragma unroll
    for (int r = 0; r < 4; r++)
        o += w[r] * g_o[(((size_t)bh * 4 + r) * T + pos) * DH + d];
    o /= ws;
    int b = bh >> 3, h = bh & 7;
    g_ctx[((size_t)b * T + pos) * DM + h * 64 + d] = o;
}

// ======== launch ========
extern "C" void kernel_launch(void* const* d_in, const int* in_sizes, int n_in,
                              void* d_out, int out_size)
{
    (void)in_sizes; (void)n_in; (void)out_size;
    const float* queries   = (const float*)d_in[0];
    const float* W_qk      = (const float*)d_in[3];
    const float* W_v       = (const float*)d_in[4];
    const float* W_out     = (const float*)d_in[5];
    const float* b_out     = (const float*)d_in[6];
    const float* rotations = (const float*)d_in[7];
    float* out = (float*)d_out;

    static cudaStream_t s_aux = nullptr;
    static cudaEvent_t ev_fork = nullptr, ev_join = nullptr;
    if (!s_aux) {
        cudaStreamCreateWithFlags(&s_aux, cudaStreamNonBlocking);
        cudaEventCreateWithFlags(&ev_fork, cudaEventDisableTiming);
        cudaEventCreateWithFlags(&ev_join, cudaEventDisableTiming);
    }

    dim3 gq(512 / 64, 16384 / 128);
    dim3 gb(512 / 128, 16384 / 128);

    cudaFuncSetAttribute(gemm_bf16_kernel<1>, cudaFuncAttributeMaxDynamicSharedMemorySize, SMEM_BF);
    cudaFuncSetAttribute(gemm_bf16_kernel<2>, cudaFuncAttributeMaxDynamicSharedMemorySize, SMEM_BF);
    cudaFuncSetAttribute(lsh_attn_mma_kernel, cudaFuncAttributeMaxDynamicSharedMemorySize, SMEM_ATTN2);

    cudaEventRecord(ev_fork, 0);
    cudaStreamWaitEvent(s_aux, ev_fork, 0);
    gemm_bf16_kernel<1><<<gb, 256, SMEM_BF, s_aux>>>(queries, W_v, nullptr, nullptr);
    cudaEventRecord(ev_join, s_aux);

    gemm_qk_kernel<<<gq, 256>>>(queries, W_qk);
    hash_sort_kernel<<<BHN * NH, 256>>>(rotations);

    cudaStreamWaitEvent(0, ev_join, 0);

    lsh_attn_mma_kernel<<<BHN * 256, 256, SMEM_ATTN2>>>();

    combine_kernel<<<(BHN * T * DH) / 256, 256>>>();

    gemm_bf16_kernel<2><<<gb, 256, SMEM_BF>>>(nullptr, W_out, b_out, out);
}